// round 12
// baseline (speedup 1.0000x reference)
#include <cuda_runtime.h>
#include <cuda_bf16.h>
#include <math.h>
#include <stdint.h>

typedef __nv_bfloat16 bf16;

// ---------------- problem constants ----------------
constexpr int SE_    = 128;
constexpr int T_     = 256;
constexpr int BATCH  = 128;
constexpr int NH     = 4;
constexpr int DFF    = 128;
constexpr int DFEAT  = 1024;
constexpr int DMODEL = 528;
constexpr int DFINAL = 1040;
constexpr int HD     = 132;
constexpr int DPAD   = 136;               // HD padded to 16B-aligned rows
constexpr int LDQ    = BATCH*3*DMODEL;    // 202752

// ---------------- fp32 scratch ----------------
__device__ float g_hg  [(size_t)BATCH*SE_*DFEAT];
__device__ float g_v   [(size_t)BATCH*SE_*DFEAT];
__device__ float g_skip[(size_t)BATCH*SE_*DFEAT];
__device__ float g_S   [(size_t)BATCH*SE_*SE_];
__device__ float g_W   [(size_t)BATCH*SE_*SE_];
__device__ float g_x   [(size_t)T_*BATCH*DMODEL];
__device__ float g_qkv [(size_t)T_*BATCH*3*DMODEL];
__device__ float g_att [(size_t)BATCH*NH*T_*T_];
__device__ float g_pool[(size_t)BATCH*DFINAL];
__device__ float g_hid [(size_t)BATCH*DFINAL];

// ---------------- bf16 hi/lo split scratch ----------------
__device__ bf16 g_hg_h [(size_t)BATCH*SE_*DFEAT];
__device__ bf16 g_hg_l [(size_t)BATCH*SE_*DFEAT];
__device__ bf16 g_q_h  [(size_t)BATCH*SE_*DFEAT];
__device__ bf16 g_q_l  [(size_t)BATCH*SE_*DFEAT];
__device__ bf16 g_k_h  [(size_t)BATCH*SE_*DFEAT];
__device__ bf16 g_k_l  [(size_t)BATCH*SE_*DFEAT];
__device__ bf16 g_vT_h [(size_t)BATCH*DFEAT*SE_];
__device__ bf16 g_vT_l [(size_t)BATCH*DFEAT*SE_];
__device__ bf16 g_E_h  [(size_t)BATCH*SE_*SE_];
__device__ bf16 g_E_l  [(size_t)BATCH*SE_*SE_];
__device__ bf16 g_x_h  [(size_t)T_*BATCH*DMODEL];
__device__ bf16 g_x_l  [(size_t)T_*BATCH*DMODEL];
__device__ bf16 g_qr_h [(size_t)BATCH*NH*T_*DPAD];
__device__ bf16 g_qr_l [(size_t)BATCH*NH*T_*DPAD];
__device__ bf16 g_kr_h [(size_t)BATCH*NH*T_*DPAD];
__device__ bf16 g_kr_l [(size_t)BATCH*NH*T_*DPAD];
__device__ bf16 g_att_h[(size_t)BATCH*NH*T_*T_];
__device__ bf16 g_att_l[(size_t)BATCH*NH*T_*T_];
__device__ bf16 g_vTt_h[(size_t)BATCH*NH*HD*T_];
__device__ bf16 g_vTt_l[(size_t)BATCH*NH*HD*T_];
__device__ bf16 g_o_h  [(size_t)T_*BATCH*DMODEL];
__device__ bf16 g_o_l  [(size_t)T_*BATCH*DMODEL];
__device__ bf16 g_ff_h [(size_t)T_*BATCH*DFF];
__device__ bf16 g_ff_l [(size_t)T_*BATCH*DFF];
__device__ bf16 g_pl_h [(size_t)BATCH*DFINAL];
__device__ bf16 g_pl_l [(size_t)BATCH*DFINAL];
__device__ bf16 g_st_h [(size_t)BATCH*64];
__device__ bf16 g_st_l [(size_t)BATCH*64];
constexpr size_t WBN = 1081600;   // >= mlp_W1 (1040*1040), >= Wqkv slice
__device__ bf16 g_w0_h[WBN]; __device__ bf16 g_w0_l[WBN];
__device__ bf16 g_w1_h[WBN]; __device__ bf16 g_w1_l[WBN];
__device__ bf16 g_w2_h[WBN]; __device__ bf16 g_w2_l[WBN];
__device__ bf16 g_w3_h[WBN]; __device__ bf16 g_w3_l[WBN];

// ---------------- helpers ----------------
__device__ __forceinline__ void split1(float v, bf16& h, bf16& l) {
    h = __float2bfloat16(v);
    l = __float2bfloat16(v - __bfloat162float(h));
}
__device__ __forceinline__ uint32_t smem_u32(const void* p) {
    uint32_t a;
    asm("{ .reg .u64 t; cvta.to.shared.u64 t, %1; cvt.u32.u64 %0, t; }" : "=r"(a) : "l"(p));
    return a;
}
// NOTE: non-volatile, no memory clobber — pure register op, lets ptxas
// interleave independent accumulator chains.
__device__ __forceinline__ void mma_bf16(float* d, const uint32_t* a, const uint32_t* b) {
    asm("mma.sync.aligned.m16n8k16.row.col.f32.bf16.bf16.f32 "
        "{%0,%1,%2,%3}, {%4,%5,%6,%7}, {%8,%9}, {%0,%1,%2,%3};"
        : "+f"(d[0]), "+f"(d[1]), "+f"(d[2]), "+f"(d[3])
        : "r"(a[0]), "r"(a[1]), "r"(a[2]), "r"(a[3]), "r"(b[0]), "r"(b[1]));
}
#define LDSM4(r0,r1,r2,r3,addr) \
    asm volatile("ldmatrix.sync.aligned.m8n8.x4.shared.b16 {%0,%1,%2,%3}, [%4];" \
        : "=r"(r0), "=r"(r1), "=r"(r2), "=r"(r3) : "r"(addr))
#define CPASYNC(dst, src, zf) \
    asm volatile("cp.async.cg.shared.global [%0], [%1], 16, %2;" \
        :: "r"(dst), "l"(src), "r"(zf) : "memory")

// =====================================================================
// HMMA 3xBF16 NT GEMM on pre-split operands.
// Block tile 128x128, K-chunk 64, 3-stage cp.async pipeline, ldmatrix.
// Inner loop is VARIANT-MAJOR: hh x16, lh x16, hl x16 -> same-acc reuse
// distance 16 independent MMAs (was 1 -> RAW-stall bound at ~37% pipe).
// =====================================================================
constexpr int TGP = 144;       // bytes per smem row
constexpr int TGT = 128*TGP;   // 18432 bytes per tile
constexpr int TGB = 4*TGT;     // Ah, Al, Bh, Bl = 73728
constexpr int TGS = 3*TGB;     // 221184 bytes (3 stages)

__global__ __launch_bounds__(256, 1) void tgemm_kernel(
    const bf16* __restrict__ Ah, const bf16* __restrict__ Al, int lda, long sA1, long sA2,
    const bf16* __restrict__ Bh, const bf16* __restrict__ Bl, int ldb, long sB1, long sB2,
    float* __restrict__ C, bf16* __restrict__ Ch, bf16* __restrict__ Cl,
    int ldc, long sC1, long sC2,
    const float* __restrict__ bias, const float* __restrict__ addend,
    float scale, int doRelu, int zdiv, int M, int N, int K)
{
    extern __shared__ char smraw[];
    uint32_t sb = smem_u32(smraw);
    int tid = threadIdx.x, wid = tid >> 5, lane = tid & 31;
    int wm = wid & 3, wn = wid >> 2;
    int g = lane >> 2, t4 = lane & 3;

    int z = blockIdx.z, z1 = z / zdiv, z2 = z % zdiv;
    const bf16* A_h = Ah + z1*sA1 + z2*sA2;
    const bf16* A_l = Al + z1*sA1 + z2*sA2;
    const bf16* B_h = Bh + z1*sB1 + z2*sB2;
    const bf16* B_l = Bl + z1*sB1 + z2*sB2;
    float* Cb = C ? C + z1*sC1 + z2*sC2 : (float*)0;
    bf16* Chb = Ch ? Ch + z1*sC1 + z2*sC2 : (bf16*)0;
    bf16* Clb = Cl ? Cl + z1*sC1 + z2*sC2 : (bf16*)0;
    const float* Db = addend ? addend + z1*sC1 + z2*sC2 : (const float*)0;

    int bm0 = blockIdx.y * 128;
    int bn0 = blockIdx.x * 128;
    int nk = (K + 63) >> 6;

    auto issue = [&](int c, int buf) {
        int k0 = c << 6;
        uint32_t bb = sb + (uint32_t)buf * TGB;
        #pragma unroll
        for (int j = 0; j < 4; j++) {
            int u = tid + j * 256;
            int rr = u >> 3, c8 = u & 7;
            int gk = k0 + c8 * 8;
            int zf = 2 * (K - gk); zf = zf < 0 ? 0 : (zf > 16 ? 16 : zf);
            uint32_t sa = bb + rr * TGP + c8 * 16;
            {
                int m = bm0 + rr;
                int z8 = (m < M) ? zf : 0;
                const bf16* ph = z8 ? (A_h + (long)m * lda + gk) : A_h;
                const bf16* pl = z8 ? (A_l + (long)m * lda + gk) : A_l;
                CPASYNC(sa,       ph, z8);
                CPASYNC(sa + TGT, pl, z8);
            }
            {
                int n = bn0 + rr;
                int z8 = (n < N) ? zf : 0;
                const bf16* ph = z8 ? (B_h + (long)n * ldb + gk) : B_h;
                const bf16* pl = z8 ? (B_l + (long)n * ldb + gk) : B_l;
                CPASYNC(sa + 2*TGT, ph, z8);
                CPASYNC(sa + 3*TGT, pl, z8);
            }
        }
        asm volatile("cp.async.commit_group;" ::: "memory");
    };

    issue(0, 0);
    if (nk > 1) issue(1, 1);

    float acc[2][8][4];
    #pragma unroll
    for (int i = 0; i < 2; i++)
        #pragma unroll
        for (int j = 0; j < 8; j++)
            #pragma unroll
            for (int d = 0; d < 4; d++) acc[i][j][d] = 0.f;

    int aRow  = wm*32 + (lane & 7) + ((lane >> 3) & 1) * 8;
    int aColB = (lane >> 4) * 16;
    int bRow  = wn*64 + (lane & 7) + (lane >> 4) * 8;
    int bColB = ((lane >> 3) & 1) * 16;

    for (int c = 0; c < nk; c++) {
        if (c + 1 < nk) asm volatile("cp.async.wait_group 1;" ::: "memory");
        else            asm volatile("cp.async.wait_group 0;" ::: "memory");
        __syncthreads();
        if (c + 2 < nk) issue(c + 2, (c + 2) % 3);

        uint32_t bb = sb + (uint32_t)(c % 3) * TGB;
        uint32_t aH = bb + aRow * TGP + aColB;
        uint32_t aL = aH + TGT;
        uint32_t bH = bb + 2*TGT + bRow * TGP + bColB;
        uint32_t bL = bH + TGT;

        int smax = (K - (c << 6) + 15) >> 4;
        if (smax > 4) smax = 4;
        #pragma unroll 4
        for (int s = 0; s < smax; s++) {
            uint32_t ah[2][4], al[2][4], bh[8][2], bl[8][2];
            #pragma unroll
            for (int mt = 0; mt < 2; mt++) {
                LDSM4(ah[mt][0], ah[mt][1], ah[mt][2], ah[mt][3], aH + mt*(16*TGP) + s*32);
                LDSM4(al[mt][0], al[mt][1], al[mt][2], al[mt][3], aL + mt*(16*TGP) + s*32);
            }
            #pragma unroll
            for (int p = 0; p < 4; p++) {
                LDSM4(bh[2*p][0], bh[2*p][1], bh[2*p+1][0], bh[2*p+1][1], bH + p*(16*TGP) + s*32);
                LDSM4(bl[2*p][0], bl[2*p][1], bl[2*p+1][0], bl[2*p+1][1], bL + p*(16*TGP) + s*32);
            }
            // variant-major: 16 independent MMAs between same-acc reuses;
            // per-acc addition order unchanged (hh, lh, hl) -> identical numerics.
            #pragma unroll
            for (int mt = 0; mt < 2; mt++)
                #pragma unroll
                for (int nt = 0; nt < 8; nt++)
                    mma_bf16(acc[mt][nt], ah[mt], bh[nt]);
            #pragma unroll
            for (int mt = 0; mt < 2; mt++)
                #pragma unroll
                for (int nt = 0; nt < 8; nt++)
                    mma_bf16(acc[mt][nt], al[mt], bh[nt]);
            #pragma unroll
            for (int mt = 0; mt < 2; mt++)
                #pragma unroll
                for (int nt = 0; nt < 8; nt++)
                    mma_bf16(acc[mt][nt], ah[mt], bl[nt]);
        }
    }

    // epilogue
    #pragma unroll
    for (int mt = 0; mt < 2; mt++) {
        int rlo = bm0 + wm*32 + mt*16 + g;
        int rhi = rlo + 8;
        #pragma unroll
        for (int nt = 0; nt < 8; nt++) {
            int c0 = bn0 + wn*64 + nt*8 + t4*2;
            #pragma unroll
            for (int hh = 0; hh < 2; hh++) {
                int row = hh ? rhi : rlo;
                if (row >= M) continue;
                #pragma unroll
                for (int cc = 0; cc < 2; cc++) {
                    int n = c0 + cc;
                    if (n >= N) continue;
                    long ci = (long)row * ldc + n;
                    float vv = acc[mt][nt][hh*2 + cc] * scale;
                    if (bias) vv += __ldg(bias + n);
                    if (Db)   vv += Db[ci];
                    if (doRelu) vv = fmaxf(vv, 0.f);
                    if (Cb) Cb[ci] = vv;
                    if (Chb) { bf16 h, l; split1(vv, h, l); Chb[ci] = h; Clb[ci] = l; }
                }
            }
        }
    }
}

// ---------------- converts / repacks ----------------
__global__ void split_kernel(const float* __restrict__ in,
                             bf16* __restrict__ h, bf16* __restrict__ l, int n)
{
    int i = blockIdx.x * 256 + threadIdx.x;
    if (i < n) { bf16 hv, lv; split1(in[i], hv, lv); h[i] = hv; l[i] = lv; }
}

// prop v [b][se][feat] -> vT [b][feat][se], split
__global__ void convT_prop_kernel(const float* __restrict__ v,
                                  bf16* __restrict__ th, bf16* __restrict__ tl)
{
    __shared__ float tile[32][33];
    int b = blockIdx.z;
    int f0 = blockIdx.x * 32, s0 = blockIdx.y * 32;
    int tx = threadIdx.x, ty = threadIdx.y;   // 32 x 8
    const float* vb = v + (long)b*SE_*DFEAT;
    #pragma unroll
    for (int k2 = 0; k2 < 4; k2++)
        tile[ty + k2*8][tx] = vb[(long)(s0 + ty + k2*8)*DFEAT + f0 + tx];
    __syncthreads();
    bf16* thb = th + (long)b*DFEAT*SE_;
    bf16* tlb = tl + (long)b*DFEAT*SE_;
    #pragma unroll
    for (int k2 = 0; k2 < 4; k2++) {
        float val = tile[tx][ty + k2*8];
        long oi = (long)(f0 + ty + k2*8)*SE_ + s0 + tx;
        bf16 h, l; split1(val, h, l); thb[oi] = h; tlb[oi] = l;
    }
}

// tran v slice of qkv -> vTt [bh][d][t], split
__global__ void convT_tran_kernel(const float* __restrict__ qkv,
                                  bf16* __restrict__ th, bf16* __restrict__ tl)
{
    __shared__ float tile[32][33];
    int bh = blockIdx.z; int b = bh >> 2, h = bh & 3;
    int t0 = blockIdx.x * 32, d0 = blockIdx.y * 32;
    int tx = threadIdx.x, ty = threadIdx.y;   // 32 x 8
    const float* base = qkv + (long)b*3*DMODEL + 2*DMODEL + h*HD;
    #pragma unroll
    for (int k2 = 0; k2 < 4; k2++) {
        int d = d0 + tx;
        tile[ty + k2*8][tx] = (d < HD) ? base[(long)(t0 + ty + k2*8)*LDQ + d] : 0.f;
    }
    __syncthreads();
    bf16* thb = th + (long)bh*HD*T_;
    bf16* tlb = tl + (long)bh*HD*T_;
    #pragma unroll
    for (int k2 = 0; k2 < 4; k2++) {
        int d = d0 + ty + k2*8;
        if (d < HD) {
            float val = tile[tx][ty + k2*8];
            long oi = (long)d*T_ + t0 + tx;
            bf16 hh, ll; split1(val, hh, ll); thb[oi] = hh; tlb[oi] = ll;
        }
    }
}

// q,k parts of qkv -> [bh][t][DPAD] split (zero-pad 132->136)
__global__ void repack_qk_kernel(const float* __restrict__ qkv,
                                 bf16* __restrict__ qh, bf16* __restrict__ ql,
                                 bf16* __restrict__ kh, bf16* __restrict__ kl)
{
    long idx = (long)blockIdx.x * 256 + threadIdx.x;
    if (idx >= (long)BATCH*NH*T_*DPAD) return;
    int d = (int)(idx % DPAD);
    long r = idx / DPAD;
    int t = (int)(r % T_);
    int bh = (int)(r / T_);
    int b = bh >> 2, h = bh & 3;
    long src = (long)t*LDQ + (long)b*3*DMODEL + h*HD;
    float qv = (d < HD) ? qkv[src + d] : 0.f;
    float kv = (d < HD) ? qkv[src + DMODEL + d] : 0.f;
    bf16 hh, ll;
    split1(qv, hh, ll); qh[idx] = hh; ql[idx] = ll;
    split1(kv, hh, ll); kh[idx] = hh; kl[idx] = ll;
}

// ---------------- elementwise / reduction kernels ---------------------------
__global__ void build_hg_kernel(const float* __restrict__ src,
                                const float* __restrict__ R_u,
                                float* __restrict__ hg,
                                bf16* __restrict__ hh, bf16* __restrict__ hl)
{
    int idx = blockIdx.x * blockDim.x + threadIdx.x;
    if (idx >= T_*BATCH*SE_) return;
    int se = idx % SE_;
    int tb = idx / SE_;
    int b = tb % BATCH;
    int t = tb / BATCH;
    float s = src[(long)t*BATCH*2*SE_ + (long)b*2*SE_ + se];
    long base = (long)b*SE_*DFEAT + (long)se*DFEAT + t*4;
    #pragma unroll
    for (int d = 0; d < 4; d++) {
        float v = fmaxf(s * R_u[se*4 + d], 0.f);
        hg[base + d] = v;
        bf16 h, l; split1(v, h, l); hh[base + d] = h; hl[base + d] = l;
    }
}

__global__ __launch_bounds__(128) void softmax_prop_kernel(
    float* __restrict__ S, float* __restrict__ W,
    bf16* __restrict__ Eh, bf16* __restrict__ El, int useW)
{
    int row = blockIdx.x;
    float* sr = S + (long)row*SE_;
    float* wr = W + (long)row*SE_;
    int tid = threadIdx.x;
    float v = sr[tid];
    __shared__ float red[4];
    float m = v;
    #pragma unroll
    for (int o = 16; o > 0; o >>= 1) m = fmaxf(m, __shfl_xor_sync(0xffffffffu, m, o));
    if ((tid & 31) == 0) red[tid >> 5] = m;
    __syncthreads();
    m = fmaxf(fmaxf(red[0], red[1]), fmaxf(red[2], red[3]));
    float e = expf(v - m);
    float s = e;
    #pragma unroll
    for (int o = 16; o > 0; o >>= 1) s += __shfl_xor_sync(0xffffffffu, s, o);
    __syncthreads();
    if ((tid & 31) == 0) red[tid >> 5] = s;
    __syncthreads();
    s = red[0] + red[1] + red[2] + red[3];
    float alpha = e / s;
    float wprev = useW ? wr[tid] : 1.0f;
    float E = alpha * wprev;
    bf16 h, l; split1(E, h, l);
    Eh[(long)row*SE_ + tid] = h;
    El[(long)row*SE_ + tid] = l;
    wr[tid] = alpha;
}

__global__ void build_x_kernel(const float* __restrict__ hg,
                               const float* __restrict__ times,
                               float* __restrict__ x,
                               bf16* __restrict__ xh, bf16* __restrict__ xl)
{
    long idx = (long)blockIdx.x * blockDim.x + threadIdx.x;
    if (idx >= (long)T_*BATCH*DMODEL) return;
    int c = (int)(idx % DMODEL);
    long tb = idx / DMODEL;
    int b = (int)(tb % BATCH);
    int t = (int)(tb / BATCH);
    float v;
    if (c < 512) {
        int se = c >> 2, d = c & 3;
        v = hg[(long)b*SE_*DFEAT + (long)se*DFEAT + t*4 + d];
    } else {
        int i = c - 512;
        int ii = (i < 8) ? i : i - 8;
        float tsv = powf(256.0f, (float)ii * (1.0f/7.0f));
        float st = times[(long)t*BATCH + b] / tsv;
        v = (i < 8) ? sinf(st) : cosf(st);
    }
    x[idx] = v;
    bf16 h, l; split1(v, h, l); xh[idx] = h; xl[idx] = l;
}

__global__ __launch_bounds__(256) void softmax_att_kernel(
    const float* __restrict__ S, const int* __restrict__ lengths,
    bf16* __restrict__ Ah, bf16* __restrict__ Alo)
{
    int row = blockIdx.x;
    int b = row >> 10;
    int len = lengths[b];
    const float* sr = S + (long)row*T_;
    int tid = threadIdx.x;
    float v = (tid < len) ? sr[tid] : -1e9f;
    __shared__ float red[8];
    float m = v;
    #pragma unroll
    for (int o = 16; o > 0; o >>= 1) m = fmaxf(m, __shfl_xor_sync(0xffffffffu, m, o));
    if ((tid & 31) == 0) red[tid >> 5] = m;
    __syncthreads();
    m = red[0];
    #pragma unroll
    for (int i = 1; i < 8; i++) m = fmaxf(m, red[i]);
    float e = expf(v - m);
    float s = e;
    #pragma unroll
    for (int o = 16; o > 0; o >>= 1) s += __shfl_xor_sync(0xffffffffu, s, o);
    __syncthreads();
    if ((tid & 31) == 0) red[tid >> 5] = s;
    __syncthreads();
    s = 0.f;
    #pragma unroll
    for (int i = 0; i < 8; i++) s += red[i];
    float a = e / s;
    bf16 h, l; split1(a, h, l);
    Ah[(long)row*T_ + tid] = h;
    Alo[(long)row*T_ + tid] = l;
}

__global__ __launch_bounds__(256) void add_ln_kernel(
    const float* __restrict__ xin, const float* __restrict__ res,
    const float* __restrict__ g, const float* __restrict__ be,
    float* __restrict__ out, bf16* __restrict__ oh, bf16* __restrict__ ol)
{
    int row = blockIdx.x;
    const float* xr = xin + (long)row*DMODEL;
    const float* rr = res + (long)row*DMODEL;
    float* orow = out + (long)row*DMODEL;
    __shared__ float red[256];
    int tid = threadIdx.x;
    float vals[3];
    float s = 0.f;
    #pragma unroll
    for (int i = 0; i < 3; i++) {
        int c = tid + i*256;
        float v = 0.f;
        if (c < DMODEL) v = xr[c] + rr[c];
        vals[i] = v;
        s += v;
    }
    red[tid] = s; __syncthreads();
    for (int o = 128; o > 0; o >>= 1) { if (tid < o) red[tid] += red[tid+o]; __syncthreads(); }
    float mean = red[0] * (1.0f/DMODEL);
    __syncthreads();
    float vs = 0.f;
    #pragma unroll
    for (int i = 0; i < 3; i++) {
        int c = tid + i*256;
        if (c < DMODEL) { float d = vals[i] - mean; vs += d*d; }
    }
    red[tid] = vs; __syncthreads();
    for (int o = 128; o > 0; o >>= 1) { if (tid < o) red[tid] += red[tid+o]; __syncthreads(); }
    float rstd = rsqrtf(red[0] * (1.0f/DMODEL) + 1e-5f);
    #pragma unroll
    for (int i = 0; i < 3; i++) {
        int c = tid + i*256;
        if (c < DMODEL) {
            float v = (vals[i] - mean) * rstd * g[c] + be[c];
            orow[c] = v;
            bf16 h, l; split1(v, h, l);
            oh[(long)row*DMODEL + c] = h;
            ol[(long)row*DMODEL + c] = l;
        }
    }
}

__global__ void pool_kernel(const float* __restrict__ x,
                            const int* __restrict__ lengths,
                            float* __restrict__ pooled,
                            bf16* __restrict__ ph, bf16* __restrict__ pl)
{
    int b = blockIdx.x;
    int c = blockIdx.y * 132 + threadIdx.x;
    if (threadIdx.x >= 132 || c >= DMODEL) return;
    int len = lengths[b];
    float s = 0.f;
    for (int t = 0; t < len; t++)
        s += x[(long)t*BATCH*DMODEL + (long)b*DMODEL + c];
    float v = s / ((float)len + 1.0f);
    long oi = (long)b*DFINAL + c;
    pooled[oi] = v;
    bf16 h, l; split1(v, h, l); ph[oi] = h; pl[oi] = l;
}

__global__ __launch_bounds__(256) void final_out_kernel(
    const float* __restrict__ hid, const float* __restrict__ W2,
    const float* __restrict__ b2, float* __restrict__ out)
{
    int p = blockIdx.x * 8 + (threadIdx.x >> 5);
    if (p >= BATCH*2) return;
    int b = p >> 1, c = p & 1;
    int lane = threadIdx.x & 31;
    float s = 0.f;
    for (int k = lane; k < DFINAL; k += 32)
        s += hid[(long)b*DFINAL + k] * W2[(long)c*DFINAL + k];
    #pragma unroll
    for (int o = 16; o > 0; o >>= 1) s += __shfl_xor_sync(0xffffffffu, s, o);
    if (lane == 0) out[p] = s + b2[c];
}

// ---------------- host helpers ----------------
static void tgemm(const bf16* Ah, const bf16* Al, int lda, long sA1, long sA2,
                  const bf16* Bh, const bf16* Bl, int ldb, long sB1, long sB2,
                  float* C, bf16* Ch, bf16* Cl, int ldc, long sC1, long sC2,
                  const float* bias, const float* add, float scale, int relu,
                  int zdiv, int nz, int M, int N, int K)
{
    dim3 grid((N+127)/128, (M+127)/128, nz);
    tgemm_kernel<<<grid, 256, TGS>>>(Ah, Al, lda, sA1, sA2, Bh, Bl, ldb, sB1, sB2,
                                     C, Ch, Cl, ldc, sC1, sC2, bias, add, scale,
                                     relu, zdiv, M, N, K);
}
static void wsplit(const float* in, bf16* h, bf16* l, int n) {
    split_kernel<<<(n+255)/256, 256>>>(in, h, l, n);
}

extern "C" void kernel_launch(void* const* d_in, const int* in_sizes, int n_in,
                              void* d_out, int out_size)
{
    const float* src      = (const float*)d_in[0];
    const float* times    = (const float*)d_in[1];
    const int*   lengths  = (const int*)  d_in[2];
    const float* stat     = (const float*)d_in[3];
    const float* R_u      = (const float*)d_in[4];
    const float* static_W = (const float*)d_in[5];
    const float* static_b = (const float*)d_in[6];
    const float* p_Wq     = (const float*)d_in[7];
    const float* p_Wk     = (const float*)d_in[8];
    const float* p_Wv     = (const float*)d_in[9];
    const float* p_bq     = (const float*)d_in[10];
    const float* p_bk     = (const float*)d_in[11];
    const float* p_bv     = (const float*)d_in[12];
    const float* p_Wskip  = (const float*)d_in[13];
    const float* p_bskip  = (const float*)d_in[14];
    const float* t_Wqkv   = (const float*)d_in[15];
    const float* t_bqkv   = (const float*)d_in[16];
    const float* t_Wo     = (const float*)d_in[17];
    const float* t_bo     = (const float*)d_in[18];
    const float* t_W1     = (const float*)d_in[19];
    const float* t_b1     = (const float*)d_in[20];
    const float* t_W2     = (const float*)d_in[21];
    const float* t_b2     = (const float*)d_in[22];
    const float* t_ln1g   = (const float*)d_in[23];
    const float* t_ln1b   = (const float*)d_in[24];
    const float* t_ln2g   = (const float*)d_in[25];
    const float* t_ln2b   = (const float*)d_in[26];
    const float* mlp_W1   = (const float*)d_in[27];
    const float* mlp_b1   = (const float*)d_in[28];
    const float* mlp_W2   = (const float*)d_in[29];
    const float* mlp_b2   = (const float*)d_in[30];
    float* out = (float*)d_out;

    cudaFuncSetAttribute(tgemm_kernel, cudaFuncAttributeMaxDynamicSharedMemorySize, TGS);

    float *hg,*v,*skip,*S,*W,*x,*qkv,*att,*pooled,*hid;
    cudaGetSymbolAddress((void**)&hg,g_hg);
    cudaGetSymbolAddress((void**)&v,g_v);
    cudaGetSymbolAddress((void**)&skip,g_skip); cudaGetSymbolAddress((void**)&S,g_S);
    cudaGetSymbolAddress((void**)&W,g_W);   cudaGetSymbolAddress((void**)&x,g_x);
    cudaGetSymbolAddress((void**)&qkv,g_qkv); cudaGetSymbolAddress((void**)&att,g_att);
    cudaGetSymbolAddress((void**)&pooled,g_pool); cudaGetSymbolAddress((void**)&hid,g_hid);

    bf16 *hgh,*hgl,*qh,*ql,*kh,*kl,*vTh,*vTl,*Eh,*El,*xh,*xl;
    bf16 *qrh,*qrl,*krh,*krl,*atth,*attl,*vTth,*vTtl,*oh,*ol,*ffh,*ffl,*plh,*pll,*sth,*stl;
    bf16 *w0h,*w0l,*w1h,*w1l,*w2h,*w2l,*w3h,*w3l;
    cudaGetSymbolAddress((void**)&hgh,g_hg_h); cudaGetSymbolAddress((void**)&hgl,g_hg_l);
    cudaGetSymbolAddress((void**)&qh,g_q_h);   cudaGetSymbolAddress((void**)&ql,g_q_l);
    cudaGetSymbolAddress((void**)&kh,g_k_h);   cudaGetSymbolAddress((void**)&kl,g_k_l);
    cudaGetSymbolAddress((void**)&vTh,g_vT_h); cudaGetSymbolAddress((void**)&vTl,g_vT_l);
    cudaGetSymbolAddress((void**)&Eh,g_E_h);   cudaGetSymbolAddress((void**)&El,g_E_l);
    cudaGetSymbolAddress((void**)&xh,g_x_h);   cudaGetSymbolAddress((void**)&xl,g_x_l);
    cudaGetSymbolAddress((void**)&qrh,g_qr_h); cudaGetSymbolAddress((void**)&qrl,g_qr_l);
    cudaGetSymbolAddress((void**)&krh,g_kr_h); cudaGetSymbolAddress((void**)&krl,g_kr_l);
    cudaGetSymbolAddress((void**)&atth,g_att_h); cudaGetSymbolAddress((void**)&attl,g_att_l);
    cudaGetSymbolAddress((void**)&vTth,g_vTt_h); cudaGetSymbolAddress((void**)&vTtl,g_vTt_l);
    cudaGetSymbolAddress((void**)&oh,g_o_h);   cudaGetSymbolAddress((void**)&ol,g_o_l);
    cudaGetSymbolAddress((void**)&ffh,g_ff_h); cudaGetSymbolAddress((void**)&ffl,g_ff_l);
    cudaGetSymbolAddress((void**)&plh,g_pl_h); cudaGetSymbolAddress((void**)&pll,g_pl_l);
    cudaGetSymbolAddress((void**)&sth,g_st_h); cudaGetSymbolAddress((void**)&stl,g_st_l);
    cudaGetSymbolAddress((void**)&w0h,g_w0_h); cudaGetSymbolAddress((void**)&w0l,g_w0_l);
    cudaGetSymbolAddress((void**)&w1h,g_w1_h); cudaGetSymbolAddress((void**)&w1l,g_w1_l);
    cudaGetSymbolAddress((void**)&w2h,g_w2_h); cudaGetSymbolAddress((void**)&w2l,g_w2_l);
    cudaGetSymbolAddress((void**)&w3h,g_w3_h); cudaGetSymbolAddress((void**)&w3l,g_w3_l);

    const int M1 = BATCH*SE_;   // 16384
    const int MT = T_*BATCH;    // 32768

    build_hg_kernel<<<(T_*BATCH*SE_ + 255)/256, 256>>>(src, R_u, hg, hgh, hgl);

    // ---------------- prop layers ----------------
    for (int l = 0; l < 2; l++) {
        long wOff = (long)l*DFEAT*DFEAT;
        long bOff = (long)l*DFEAT;
        wsplit(p_Wq + wOff,    w0h, w0l, DFEAT*DFEAT);
        wsplit(p_Wk + wOff,    w1h, w1l, DFEAT*DFEAT);
        wsplit(p_Wv + wOff,    w2h, w2l, DFEAT*DFEAT);
        wsplit(p_Wskip + wOff, w3h, w3l, DFEAT*DFEAT);
        tgemm(hgh, hgl, DFEAT, 0,0, w0h, w0l, DFEAT, 0,0,
              0, qh, ql, DFEAT, 0,0, p_bq + bOff, 0, 1.f, 0, 1, 1, M1, DFEAT, DFEAT);
        tgemm(hgh, hgl, DFEAT, 0,0, w1h, w1l, DFEAT, 0,0,
              0, kh, kl, DFEAT, 0,0, p_bk + bOff, 0, 1.f, 0, 1, 1, M1, DFEAT, DFEAT);
        tgemm(hgh, hgl, DFEAT, 0,0, w2h, w2l, DFEAT, 0,0,
              v, 0, 0, DFEAT, 0,0, p_bv + bOff, 0, 1.f, 0, 1, 1, M1, DFEAT, DFEAT);
        tgemm(hgh, hgl, DFEAT, 0,0, w3h, w3l, DFEAT, 0,0,
              skip, 0, 0, DFEAT, 0,0, p_bskip + bOff, 0, 1.f, 0, 1, 1, M1, DFEAT, DFEAT);
        // scores[b] = q[b] @ k[b]^T / 32
        tgemm(qh, ql, DFEAT, (long)SE_*DFEAT, 0, kh, kl, DFEAT, (long)SE_*DFEAT, 0,
              S, 0, 0, SE_, (long)SE_*SE_, 0, 0, 0, 0.03125f, 0, 1, BATCH,
              SE_, SE_, DFEAT);
        softmax_prop_kernel<<<BATCH*SE_, 128>>>(S, W, Eh, El, l > 0);
        convT_prop_kernel<<<dim3(DFEAT/32, SE_/32, BATCH), dim3(32,8)>>>(v, vTh, vTl);
        // hg = E @ vT^T + skip
        tgemm(Eh, El, SE_, (long)SE_*SE_, 0, vTh, vTl, SE_, (long)DFEAT*SE_, 0,
              hg, hgh, hgl, DFEAT, (long)SE_*DFEAT, 0, 0, skip, 1.f, 0, 1, BATCH,
              SE_, DFEAT, SE_);
    }

    build_x_kernel<<<(int)(((long)T_*BATCH*DMODEL + 255)/256), 256>>>(hg, times, x, xh, xl);

    const float attScale = 1.0f / sqrtf((float)HD);

    // ---------------- transformer layers ----------------
    for (int l = 0; l < 2; l++) {
        wsplit(t_Wqkv + (long)l*3*DMODEL*DMODEL, w0h, w0l, 3*DMODEL*DMODEL);
        wsplit(t_Wo   + (long)l*DMODEL*DMODEL,   w1h, w1l, DMODEL*DMODEL);
        wsplit(t_W1   + (long)l*DFF*DMODEL,      w2h, w2l, DFF*DMODEL);
        wsplit(t_W2   + (long)l*DMODEL*DFF,      w3h, w3l, DMODEL*DFF);

        tgemm(xh, xl, DMODEL, 0,0, w0h, w0l, DMODEL, 0,0,
              qkv, 0, 0, 3*DMODEL, 0,0, t_bqkv + (long)l*3*DMODEL, 0, 1.f, 0, 1, 1,
              MT, 3*DMODEL, DMODEL);
        repack_qk_kernel<<<(int)(((long)BATCH*NH*T_*DPAD + 255)/256), 256>>>(
            qkv, qrh, qrl, krh, krl);
        // att scores
        tgemm(qrh, qrl, DPAD, (long)T_*DPAD, 0, krh, krl, DPAD, (long)T_*DPAD, 0,
              att, 0, 0, T_, (long)T_*T_, 0, 0, 0, attScale, 0, 1, BATCH*NH,
              T_, T_, DPAD);
        softmax_att_kernel<<<BATCH*NH*T_, 256>>>(att, lengths, atth, attl);
        convT_tran_kernel<<<dim3(T_/32, (HD+31)/32, BATCH*NH), dim3(32,8)>>>(qkv, vTth, vTtl);
        // o = att @ vTt^T  (split outputs only)
        tgemm(atth, attl, T_, (long)NH*T_*T_, (long)T_*T_,
              vTth, vTtl, T_, (long)NH*HD*T_, (long)HD*T_,
              0, oh, ol, BATCH*DMODEL, DMODEL, HD,
              0, 0, 1.f, 0, NH, BATCH*NH, T_, HD, T_);
        // o2 = o @ Wo^T + bo (into qkv scratch)
        tgemm(oh, ol, DMODEL, 0,0, w1h, w1l, DMODEL, 0,0,
              qkv, 0, 0, DMODEL, 0,0, t_bo + (long)l*DMODEL, 0, 1.f, 0, 1, 1,
              MT, DMODEL, DMODEL);
        add_ln_kernel<<<MT, 256>>>(x, qkv, t_ln1g + (long)l*DMODEL,
                                   t_ln1b + (long)l*DMODEL, x, xh, xl);
        tgemm(xh, xl, DMODEL, 0,0, w2h, w2l, DMODEL, 0,0,
              0, ffh, ffl, DFF, 0,0, t_b1 + (long)l*DFF, 0, 1.f, 1, 1, 1,
              MT, DFF, DMODEL);
        tgemm(ffh, ffl, DFF, 0,0, w3h, w3l, DFF, 0,0,
              qkv, 0, 0, DMODEL, 0,0, t_b2 + (long)l*DMODEL, 0, 1.f, 0, 1, 1,
              MT, DMODEL, DFF);
        add_ln_kernel<<<MT, 256>>>(x, qkv, t_ln2g + (long)l*DMODEL,
                                   t_ln2b + (long)l*DMODEL, x, xh, xl);
    }

    // ---------------- head ----------------
    pool_kernel<<<dim3(BATCH, 4), 132>>>(x, lengths, pooled, plh, pll);
    wsplit(stat, sth, stl, BATCH*64);
    wsplit(static_W, w0h, w0l, 512*64);
    tgemm(sth, stl, 64, 0,0, w0h, w0l, 64, 0,0,
          0, plh + DMODEL, pll + DMODEL, DFINAL, 0,0,
          static_b, 0, 1.f, 0, 1, 1, BATCH, 512, 64);
    wsplit(mlp_W1, w1h, w1l, DFINAL*DFINAL);
    tgemm(plh, pll, DFINAL, 0,0, w1h, w1l, DFINAL, 0,0,
          hid, 0, 0, DFINAL, 0,0, mlp_b1, 0, 1.f, 1, 1, 1, BATCH, DFINAL, DFINAL);
    final_out_kernel<<<32, 256>>>(hid, mlp_W2, mlp_b2, out);
    (void)in_sizes; (void)n_in; (void)out_size;
}

// round 13
// speedup vs baseline: 1.2524x; 1.2524x over previous
#include <cuda_runtime.h>
#include <cuda_fp16.h>
#include <math.h>
#include <stdint.h>

typedef __half f16;

// ---------------- problem constants ----------------
constexpr int SE_    = 128;
constexpr int T_     = 256;
constexpr int BATCH  = 128;
constexpr int NH     = 4;
constexpr int DFF    = 128;
constexpr int DFEAT  = 1024;
constexpr int DMODEL = 528;
constexpr int DFINAL = 1040;
constexpr int HD     = 132;
constexpr int DPAD   = 136;               // HD padded to 16B-aligned rows
constexpr int LDQ    = BATCH*3*DMODEL;    // 202752

// ---------------- fp32 scratch ----------------
__device__ float g_hg  [(size_t)BATCH*SE_*DFEAT];
__device__ float g_v   [(size_t)BATCH*SE_*DFEAT];
__device__ float g_skip[(size_t)BATCH*SE_*DFEAT];
__device__ float g_S   [(size_t)BATCH*SE_*SE_];
__device__ float g_W   [(size_t)BATCH*SE_*SE_];
__device__ float g_x   [(size_t)T_*BATCH*DMODEL];
__device__ float g_qkv [(size_t)T_*BATCH*3*DMODEL];
__device__ float g_att [(size_t)BATCH*NH*T_*T_];
__device__ float g_pool[(size_t)BATCH*DFINAL];
__device__ float g_hid [(size_t)BATCH*DFINAL];

// ---------------- fp16 hi/lo split scratch ----------------
__device__ f16 g_hg_h [(size_t)BATCH*SE_*DFEAT];
__device__ f16 g_hg_l [(size_t)BATCH*SE_*DFEAT];
__device__ f16 g_q_h  [(size_t)BATCH*SE_*DFEAT];
__device__ f16 g_q_l  [(size_t)BATCH*SE_*DFEAT];
__device__ f16 g_k_h  [(size_t)BATCH*SE_*DFEAT];
__device__ f16 g_k_l  [(size_t)BATCH*SE_*DFEAT];
__device__ f16 g_vT_h [(size_t)BATCH*DFEAT*SE_];
__device__ f16 g_vT_l [(size_t)BATCH*DFEAT*SE_];
__device__ f16 g_E_h  [(size_t)BATCH*SE_*SE_];
__device__ f16 g_E_l  [(size_t)BATCH*SE_*SE_];
__device__ f16 g_x_h  [(size_t)T_*BATCH*DMODEL];
__device__ f16 g_x_l  [(size_t)T_*BATCH*DMODEL];
__device__ f16 g_qr_h [(size_t)BATCH*NH*T_*DPAD];
__device__ f16 g_qr_l [(size_t)BATCH*NH*T_*DPAD];
__device__ f16 g_kr_h [(size_t)BATCH*NH*T_*DPAD];
__device__ f16 g_kr_l [(size_t)BATCH*NH*T_*DPAD];
__device__ f16 g_att_h[(size_t)BATCH*NH*T_*T_];
__device__ f16 g_att_l[(size_t)BATCH*NH*T_*T_];
__device__ f16 g_vTt_h[(size_t)BATCH*NH*HD*T_];
__device__ f16 g_vTt_l[(size_t)BATCH*NH*HD*T_];
__device__ f16 g_o_h  [(size_t)T_*BATCH*DMODEL];
__device__ f16 g_o_l  [(size_t)T_*BATCH*DMODEL];
__device__ f16 g_ff_h [(size_t)T_*BATCH*DFF];
__device__ f16 g_ff_l [(size_t)T_*BATCH*DFF];
__device__ f16 g_pl_h [(size_t)BATCH*DFINAL];
__device__ f16 g_pl_l [(size_t)BATCH*DFINAL];
__device__ f16 g_st_h [(size_t)BATCH*64];
__device__ f16 g_st_l [(size_t)BATCH*64];
constexpr size_t WBN = 1081600;   // >= mlp_W1 (1040*1040), >= Wqkv slice
__device__ f16 g_w0_h[WBN]; __device__ f16 g_w0_l[WBN];
__device__ f16 g_w1_h[WBN]; __device__ f16 g_w1_l[WBN];
__device__ f16 g_w2_h[WBN]; __device__ f16 g_w2_l[WBN];
__device__ f16 g_w3_h[WBN]; __device__ f16 g_w3_l[WBN];

// ---------------- helpers ----------------
__device__ __forceinline__ void split1(float v, f16& h, f16& l) {
    h = __float2half_rn(v);
    l = __float2half_rn(v - __half2float(h));
}
__device__ __forceinline__ uint32_t smem_u32(const void* p) {
    uint32_t a;
    asm("{ .reg .u64 t; cvta.to.shared.u64 t, %1; cvt.u32.u64 %0, t; }" : "=r"(a) : "l"(p));
    return a;
}
__device__ __forceinline__ void mma_f16(float* d, const uint32_t* a, const uint32_t* b) {
    asm("mma.sync.aligned.m16n8k16.row.col.f32.f16.f16.f32 "
        "{%0,%1,%2,%3}, {%4,%5,%6,%7}, {%8,%9}, {%0,%1,%2,%3};"
        : "+f"(d[0]), "+f"(d[1]), "+f"(d[2]), "+f"(d[3])
        : "r"(a[0]), "r"(a[1]), "r"(a[2]), "r"(a[3]), "r"(b[0]), "r"(b[1]));
}
#define LDSM4(r0,r1,r2,r3,addr) \
    asm volatile("ldmatrix.sync.aligned.m8n8.x4.shared.b16 {%0,%1,%2,%3}, [%4];" \
        : "=r"(r0), "=r"(r1), "=r"(r2), "=r"(r3) : "r"(addr))
#define CPASYNC(dst, src, zf) \
    asm volatile("cp.async.cg.shared.global [%0], [%1], 16, %2;" \
        :: "r"(dst), "l"(src), "r"(zf) : "memory")

// =====================================================================
// HMMA 2xFP16 NT GEMM on pre-split operands.
// acc += Ah*Bh + Al*Bh (A-residual corrected; B rounding ~2^-13 rel).
// Block tile 128x128, K-chunk 64, 3-stage cp.async pipeline, ldmatrix.
// =====================================================================
constexpr int TGP = 144;       // bytes per smem row
constexpr int TGT = 128*TGP;   // 18432 bytes per tile
constexpr int TGB = 3*TGT;     // Ah, Al, Bh = 55296
constexpr int TGS = 3*TGB;     // 165888 bytes (3 stages)

__global__ __launch_bounds__(256, 1) void tgemm_kernel(
    const f16* __restrict__ Ah, const f16* __restrict__ Al, int lda, long sA1, long sA2,
    const f16* __restrict__ Bh, int ldb, long sB1, long sB2,
    float* __restrict__ C, f16* __restrict__ Ch, f16* __restrict__ Cl,
    int ldc, long sC1, long sC2,
    const float* __restrict__ bias, const float* __restrict__ addend,
    float scale, int doRelu, int zdiv, int M, int N, int K)
{
    extern __shared__ char smraw[];
    uint32_t sb = smem_u32(smraw);
    int tid = threadIdx.x, wid = tid >> 5, lane = tid & 31;
    int wm = wid & 3, wn = wid >> 2;
    int g = lane >> 2, t4 = lane & 3;

    int z = blockIdx.z, z1 = z / zdiv, z2 = z % zdiv;
    const f16* A_h = Ah + z1*sA1 + z2*sA2;
    const f16* A_l = Al + z1*sA1 + z2*sA2;
    const f16* B_h = Bh + z1*sB1 + z2*sB2;
    float* Cb = C ? C + z1*sC1 + z2*sC2 : (float*)0;
    f16* Chb = Ch ? Ch + z1*sC1 + z2*sC2 : (f16*)0;
    f16* Clb = Cl ? Cl + z1*sC1 + z2*sC2 : (f16*)0;
    const float* Db = addend ? addend + z1*sC1 + z2*sC2 : (const float*)0;

    int bm0 = blockIdx.y * 128;
    int bn0 = blockIdx.x * 128;
    int nk = (K + 63) >> 6;

    auto issue = [&](int c, int buf) {
        int k0 = c << 6;
        uint32_t bb = sb + (uint32_t)buf * TGB;
        #pragma unroll
        for (int j = 0; j < 4; j++) {
            int u = tid + j * 256;
            int rr = u >> 3, c8 = u & 7;
            int gk = k0 + c8 * 8;
            int zf = 2 * (K - gk); zf = zf < 0 ? 0 : (zf > 16 ? 16 : zf);
            uint32_t sa = bb + rr * TGP + c8 * 16;
            {
                int m = bm0 + rr;
                int z8 = (m < M) ? zf : 0;
                const f16* ph = z8 ? (A_h + (long)m * lda + gk) : A_h;
                const f16* pl = z8 ? (A_l + (long)m * lda + gk) : A_l;
                CPASYNC(sa,       ph, z8);
                CPASYNC(sa + TGT, pl, z8);
            }
            {
                int n = bn0 + rr;
                int z8 = (n < N) ? zf : 0;
                const f16* ph = z8 ? (B_h + (long)n * ldb + gk) : B_h;
                CPASYNC(sa + 2*TGT, ph, z8);
            }
        }
        asm volatile("cp.async.commit_group;" ::: "memory");
    };

    issue(0, 0);
    if (nk > 1) issue(1, 1);

    float acc[2][8][4];
    #pragma unroll
    for (int i = 0; i < 2; i++)
        #pragma unroll
        for (int j = 0; j < 8; j++)
            #pragma unroll
            for (int d = 0; d < 4; d++) acc[i][j][d] = 0.f;

    int aRow  = wm*32 + (lane & 7) + ((lane >> 3) & 1) * 8;
    int aColB = (lane >> 4) * 16;
    int bRow  = wn*64 + (lane & 7) + (lane >> 4) * 8;
    int bColB = ((lane >> 3) & 1) * 16;

    for (int c = 0; c < nk; c++) {
        if (c + 1 < nk) asm volatile("cp.async.wait_group 1;" ::: "memory");
        else            asm volatile("cp.async.wait_group 0;" ::: "memory");
        __syncthreads();
        if (c + 2 < nk) issue(c + 2, (c + 2) % 3);

        uint32_t bb = sb + (uint32_t)(c % 3) * TGB;
        uint32_t aH = bb + aRow * TGP + aColB;
        uint32_t aL = aH + TGT;
        uint32_t bH = bb + 2*TGT + bRow * TGP + bColB;

        int smax = (K - (c << 6) + 15) >> 4;
        if (smax > 4) smax = 4;
        #pragma unroll 4
        for (int s = 0; s < smax; s++) {
            uint32_t ah[2][4], al[2][4], bh[8][2];
            #pragma unroll
            for (int mt = 0; mt < 2; mt++) {
                LDSM4(ah[mt][0], ah[mt][1], ah[mt][2], ah[mt][3], aH + mt*(16*TGP) + s*32);
                LDSM4(al[mt][0], al[mt][1], al[mt][2], al[mt][3], aL + mt*(16*TGP) + s*32);
            }
            #pragma unroll
            for (int p = 0; p < 4; p++) {
                LDSM4(bh[2*p][0], bh[2*p][1], bh[2*p+1][0], bh[2*p+1][1], bH + p*(16*TGP) + s*32);
            }
            #pragma unroll
            for (int mt = 0; mt < 2; mt++)
                #pragma unroll
                for (int nt = 0; nt < 8; nt++)
                    mma_f16(acc[mt][nt], ah[mt], bh[nt]);
            #pragma unroll
            for (int mt = 0; mt < 2; mt++)
                #pragma unroll
                for (int nt = 0; nt < 8; nt++)
                    mma_f16(acc[mt][nt], al[mt], bh[nt]);
        }
    }

    // epilogue
    #pragma unroll
    for (int mt = 0; mt < 2; mt++) {
        int rlo = bm0 + wm*32 + mt*16 + g;
        int rhi = rlo + 8;
        #pragma unroll
        for (int nt = 0; nt < 8; nt++) {
            int c0 = bn0 + wn*64 + nt*8 + t4*2;
            #pragma unroll
            for (int hh = 0; hh < 2; hh++) {
                int row = hh ? rhi : rlo;
                if (row >= M) continue;
                #pragma unroll
                for (int cc = 0; cc < 2; cc++) {
                    int n = c0 + cc;
                    if (n >= N) continue;
                    long ci = (long)row * ldc + n;
                    float vv = acc[mt][nt][hh*2 + cc] * scale;
                    if (bias) vv += __ldg(bias + n);
                    if (Db)   vv += Db[ci];
                    if (doRelu) vv = fmaxf(vv, 0.f);
                    if (Cb) Cb[ci] = vv;
                    if (Chb) { f16 h, l; split1(vv, h, l); Chb[ci] = h; Clb[ci] = l; }
                }
            }
        }
    }
}

// ---------------- converts / repacks ----------------
__global__ void split_kernel(const float* __restrict__ in,
                             f16* __restrict__ h, f16* __restrict__ l, int n)
{
    int i = blockIdx.x * 256 + threadIdx.x;
    if (i < n) { f16 hv, lv; split1(in[i], hv, lv); h[i] = hv; l[i] = lv; }
}

// prop v [b][se][feat] -> vT [b][feat][se], split
__global__ void convT_prop_kernel(const float* __restrict__ v,
                                  f16* __restrict__ th, f16* __restrict__ tl)
{
    __shared__ float tile[32][33];
    int b = blockIdx.z;
    int f0 = blockIdx.x * 32, s0 = blockIdx.y * 32;
    int tx = threadIdx.x, ty = threadIdx.y;   // 32 x 8
    const float* vb = v + (long)b*SE_*DFEAT;
    #pragma unroll
    for (int k2 = 0; k2 < 4; k2++)
        tile[ty + k2*8][tx] = vb[(long)(s0 + ty + k2*8)*DFEAT + f0 + tx];
    __syncthreads();
    f16* thb = th + (long)b*DFEAT*SE_;
    f16* tlb = tl + (long)b*DFEAT*SE_;
    #pragma unroll
    for (int k2 = 0; k2 < 4; k2++) {
        float val = tile[tx][ty + k2*8];
        long oi = (long)(f0 + ty + k2*8)*SE_ + s0 + tx;
        f16 h, l; split1(val, h, l); thb[oi] = h; tlb[oi] = l;
    }
}

// tran v slice of qkv -> vTt [bh][d][t], split
__global__ void convT_tran_kernel(const float* __restrict__ qkv,
                                  f16* __restrict__ th, f16* __restrict__ tl)
{
    __shared__ float tile[32][33];
    int bh = blockIdx.z; int b = bh >> 2, h = bh & 3;
    int t0 = blockIdx.x * 32, d0 = blockIdx.y * 32;
    int tx = threadIdx.x, ty = threadIdx.y;   // 32 x 8
    const float* base = qkv + (long)b*3*DMODEL + 2*DMODEL + h*HD;
    #pragma unroll
    for (int k2 = 0; k2 < 4; k2++) {
        int d = d0 + tx;
        tile[ty + k2*8][tx] = (d < HD) ? base[(long)(t0 + ty + k2*8)*LDQ + d] : 0.f;
    }
    __syncthreads();
    f16* thb = th + (long)bh*HD*T_;
    f16* tlb = tl + (long)bh*HD*T_;
    #pragma unroll
    for (int k2 = 0; k2 < 4; k2++) {
        int d = d0 + ty + k2*8;
        if (d < HD) {
            float val = tile[tx][ty + k2*8];
            long oi = (long)d*T_ + t0 + tx;
            f16 hh, ll; split1(val, hh, ll); thb[oi] = hh; tlb[oi] = ll;
        }
    }
}

// q,k parts of qkv -> [bh][t][DPAD] split (zero-pad 132->136)
__global__ void repack_qk_kernel(const float* __restrict__ qkv,
                                 f16* __restrict__ qh, f16* __restrict__ ql,
                                 f16* __restrict__ kh, f16* __restrict__ kl)
{
    long idx = (long)blockIdx.x * 256 + threadIdx.x;
    if (idx >= (long)BATCH*NH*T_*DPAD) return;
    int d = (int)(idx % DPAD);
    long r = idx / DPAD;
    int t = (int)(r % T_);
    int bh = (int)(r / T_);
    int b = bh >> 2, h = bh & 3;
    long src = (long)t*LDQ + (long)b*3*DMODEL + h*HD;
    float qv = (d < HD) ? qkv[src + d] : 0.f;
    float kv = (d < HD) ? qkv[src + DMODEL + d] : 0.f;
    f16 hh, ll;
    split1(qv, hh, ll); qh[idx] = hh; ql[idx] = ll;
    split1(kv, hh, ll); kh[idx] = hh; kl[idx] = ll;
}

// ---------------- elementwise / reduction kernels ---------------------------
__global__ void build_hg_kernel(const float* __restrict__ src,
                                const float* __restrict__ R_u,
                                float* __restrict__ hg,
                                f16* __restrict__ hh, f16* __restrict__ hl)
{
    int idx = blockIdx.x * blockDim.x + threadIdx.x;
    if (idx >= T_*BATCH*SE_) return;
    int se = idx % SE_;
    int tb = idx / SE_;
    int b = tb % BATCH;
    int t = tb / BATCH;
    float s = src[(long)t*BATCH*2*SE_ + (long)b*2*SE_ + se];
    long base = (long)b*SE_*DFEAT + (long)se*DFEAT + t*4;
    #pragma unroll
    for (int d = 0; d < 4; d++) {
        float v = fmaxf(s * R_u[se*4 + d], 0.f);
        hg[base + d] = v;
        f16 h, l; split1(v, h, l); hh[base + d] = h; hl[base + d] = l;
    }
}

__global__ __launch_bounds__(128) void softmax_prop_kernel(
    float* __restrict__ S, float* __restrict__ W,
    f16* __restrict__ Eh, f16* __restrict__ El, int useW)
{
    int row = blockIdx.x;
    float* sr = S + (long)row*SE_;
    float* wr = W + (long)row*SE_;
    int tid = threadIdx.x;
    float v = sr[tid];
    __shared__ float red[4];
    float m = v;
    #pragma unroll
    for (int o = 16; o > 0; o >>= 1) m = fmaxf(m, __shfl_xor_sync(0xffffffffu, m, o));
    if ((tid & 31) == 0) red[tid >> 5] = m;
    __syncthreads();
    m = fmaxf(fmaxf(red[0], red[1]), fmaxf(red[2], red[3]));
    float e = expf(v - m);
    float s = e;
    #pragma unroll
    for (int o = 16; o > 0; o >>= 1) s += __shfl_xor_sync(0xffffffffu, s, o);
    __syncthreads();
    if ((tid & 31) == 0) red[tid >> 5] = s;
    __syncthreads();
    s = red[0] + red[1] + red[2] + red[3];
    float alpha = e / s;
    float wprev = useW ? wr[tid] : 1.0f;
    float E = alpha * wprev;
    f16 h, l; split1(E, h, l);
    Eh[(long)row*SE_ + tid] = h;
    El[(long)row*SE_ + tid] = l;
    wr[tid] = alpha;
}

__global__ void build_x_kernel(const float* __restrict__ hg,
                               const float* __restrict__ times,
                               float* __restrict__ x,
                               f16* __restrict__ xh, f16* __restrict__ xl)
{
    long idx = (long)blockIdx.x * blockDim.x + threadIdx.x;
    if (idx >= (long)T_*BATCH*DMODEL) return;
    int c = (int)(idx % DMODEL);
    long tb = idx / DMODEL;
    int b = (int)(tb % BATCH);
    int t = (int)(tb / BATCH);
    float v;
    if (c < 512) {
        int se = c >> 2, d = c & 3;
        v = hg[(long)b*SE_*DFEAT + (long)se*DFEAT + t*4 + d];
    } else {
        int i = c - 512;
        int ii = (i < 8) ? i : i - 8;
        float tsv = powf(256.0f, (float)ii * (1.0f/7.0f));
        float st = times[(long)t*BATCH + b] / tsv;
        v = (i < 8) ? sinf(st) : cosf(st);
    }
    x[idx] = v;
    f16 h, l; split1(v, h, l); xh[idx] = h; xl[idx] = l;
}

__global__ __launch_bounds__(256) void softmax_att_kernel(
    const float* __restrict__ S, const int* __restrict__ lengths,
    f16* __restrict__ Ah, f16* __restrict__ Alo)
{
    int row = blockIdx.x;
    int b = row >> 10;
    int len = lengths[b];
    const float* sr = S + (long)row*T_;
    int tid = threadIdx.x;
    float v = (tid < len) ? sr[tid] : -1e9f;
    __shared__ float red[8];
    float m = v;
    #pragma unroll
    for (int o = 16; o > 0; o >>= 1) m = fmaxf(m, __shfl_xor_sync(0xffffffffu, m, o));
    if ((tid & 31) == 0) red[tid >> 5] = m;
    __syncthreads();
    m = red[0];
    #pragma unroll
    for (int i = 1; i < 8; i++) m = fmaxf(m, red[i]);
    float e = expf(v - m);
    float s = e;
    #pragma unroll
    for (int o = 16; o > 0; o >>= 1) s += __shfl_xor_sync(0xffffffffu, s, o);
    __syncthreads();
    if ((tid & 31) == 0) red[tid >> 5] = s;
    __syncthreads();
    s = 0.f;
    #pragma unroll
    for (int i = 0; i < 8; i++) s += red[i];
    float a = e / s;
    f16 h, l; split1(a, h, l);
    Ah[(long)row*T_ + tid] = h;
    Alo[(long)row*T_ + tid] = l;
}

__global__ __launch_bounds__(256) void add_ln_kernel(
    const float* __restrict__ xin, const float* __restrict__ res,
    const float* __restrict__ g, const float* __restrict__ be,
    float* __restrict__ out, f16* __restrict__ oh, f16* __restrict__ ol)
{
    int row = blockIdx.x;
    const float* xr = xin + (long)row*DMODEL;
    const float* rr = res + (long)row*DMODEL;
    float* orow = out + (long)row*DMODEL;
    __shared__ float red[256];
    int tid = threadIdx.x;
    float vals[3];
    float s = 0.f;
    #pragma unroll
    for (int i = 0; i < 3; i++) {
        int c = tid + i*256;
        float v = 0.f;
        if (c < DMODEL) v = xr[c] + rr[c];
        vals[i] = v;
        s += v;
    }
    red[tid] = s; __syncthreads();
    for (int o = 128; o > 0; o >>= 1) { if (tid < o) red[tid] += red[tid+o]; __syncthreads(); }
    float mean = red[0] * (1.0f/DMODEL);
    __syncthreads();
    float vs = 0.f;
    #pragma unroll
    for (int i = 0; i < 3; i++) {
        int c = tid + i*256;
        if (c < DMODEL) { float d = vals[i] - mean; vs += d*d; }
    }
    red[tid] = vs; __syncthreads();
    for (int o = 128; o > 0; o >>= 1) { if (tid < o) red[tid] += red[tid+o]; __syncthreads(); }
    float rstd = rsqrtf(red[0] * (1.0f/DMODEL) + 1e-5f);
    #pragma unroll
    for (int i = 0; i < 3; i++) {
        int c = tid + i*256;
        if (c < DMODEL) {
            float v = (vals[i] - mean) * rstd * g[c] + be[c];
            orow[c] = v;
            f16 h, l; split1(v, h, l);
            oh[(long)row*DMODEL + c] = h;
            ol[(long)row*DMODEL + c] = l;
        }
    }
}

__global__ void pool_kernel(const float* __restrict__ x,
                            const int* __restrict__ lengths,
                            float* __restrict__ pooled,
                            f16* __restrict__ ph, f16* __restrict__ pl)
{
    int b = blockIdx.x;
    int c = blockIdx.y * 132 + threadIdx.x;
    if (threadIdx.x >= 132 || c >= DMODEL) return;
    int len = lengths[b];
    float s = 0.f;
    for (int t = 0; t < len; t++)
        s += x[(long)t*BATCH*DMODEL + (long)b*DMODEL + c];
    float v = s / ((float)len + 1.0f);
    long oi = (long)b*DFINAL + c;
    pooled[oi] = v;
    f16 h, l; split1(v, h, l); ph[oi] = h; pl[oi] = l;
}

__global__ __launch_bounds__(256) void final_out_kernel(
    const float* __restrict__ hid, const float* __restrict__ W2,
    const float* __restrict__ b2, float* __restrict__ out)
{
    int p = blockIdx.x * 8 + (threadIdx.x >> 5);
    if (p >= BATCH*2) return;
    int b = p >> 1, c = p & 1;
    int lane = threadIdx.x & 31;
    float s = 0.f;
    for (int k = lane; k < DFINAL; k += 32)
        s += hid[(long)b*DFINAL + k] * W2[(long)c*DFINAL + k];
    #pragma unroll
    for (int o = 16; o > 0; o >>= 1) s += __shfl_xor_sync(0xffffffffu, s, o);
    if (lane == 0) out[p] = s + b2[c];
}

// ---------------- host helpers ----------------
static void tgemm(const f16* Ah, const f16* Al, int lda, long sA1, long sA2,
                  const f16* Bh, int ldb, long sB1, long sB2,
                  float* C, f16* Ch, f16* Cl, int ldc, long sC1, long sC2,
                  const float* bias, const float* add, float scale, int relu,
                  int zdiv, int nz, int M, int N, int K)
{
    dim3 grid((N+127)/128, (M+127)/128, nz);
    tgemm_kernel<<<grid, 256, TGS>>>(Ah, Al, lda, sA1, sA2, Bh, ldb, sB1, sB2,
                                     C, Ch, Cl, ldc, sC1, sC2, bias, add, scale,
                                     relu, zdiv, M, N, K);
}
static void wsplit(const float* in, f16* h, f16* l, int n) {
    split_kernel<<<(n+255)/256, 256>>>(in, h, l, n);
}

extern "C" void kernel_launch(void* const* d_in, const int* in_sizes, int n_in,
                              void* d_out, int out_size)
{
    const float* src      = (const float*)d_in[0];
    const float* times    = (const float*)d_in[1];
    const int*   lengths  = (const int*)  d_in[2];
    const float* stat     = (const float*)d_in[3];
    const float* R_u      = (const float*)d_in[4];
    const float* static_W = (const float*)d_in[5];
    const float* static_b = (const float*)d_in[6];
    const float* p_Wq     = (const float*)d_in[7];
    const float* p_Wk     = (const float*)d_in[8];
    const float* p_Wv     = (const float*)d_in[9];
    const float* p_bq     = (const float*)d_in[10];
    const float* p_bk     = (const float*)d_in[11];
    const float* p_bv     = (const float*)d_in[12];
    const float* p_Wskip  = (const float*)d_in[13];
    const float* p_bskip  = (const float*)d_in[14];
    const float* t_Wqkv   = (const float*)d_in[15];
    const float* t_bqkv   = (const float*)d_in[16];
    const float* t_Wo     = (const float*)d_in[17];
    const float* t_bo     = (const float*)d_in[18];
    const float* t_W1     = (const float*)d_in[19];
    const float* t_b1     = (const float*)d_in[20];
    const float* t_W2     = (const float*)d_in[21];
    const float* t_b2     = (const float*)d_in[22];
    const float* t_ln1g   = (const float*)d_in[23];
    const float* t_ln1b   = (const float*)d_in[24];
    const float* t_ln2g   = (const float*)d_in[25];
    const float* t_ln2b   = (const float*)d_in[26];
    const float* mlp_W1   = (const float*)d_in[27];
    const float* mlp_b1   = (const float*)d_in[28];
    const float* mlp_W2   = (const float*)d_in[29];
    const float* mlp_b2   = (const float*)d_in[30];
    float* out = (float*)d_out;

    cudaFuncSetAttribute(tgemm_kernel, cudaFuncAttributeMaxDynamicSharedMemorySize, TGS);

    float *hg,*v,*skip,*S,*W,*x,*qkv,*att,*pooled,*hid;
    cudaGetSymbolAddress((void**)&hg,g_hg);
    cudaGetSymbolAddress((void**)&v,g_v);
    cudaGetSymbolAddress((void**)&skip,g_skip); cudaGetSymbolAddress((void**)&S,g_S);
    cudaGetSymbolAddress((void**)&W,g_W);   cudaGetSymbolAddress((void**)&x,g_x);
    cudaGetSymbolAddress((void**)&qkv,g_qkv); cudaGetSymbolAddress((void**)&att,g_att);
    cudaGetSymbolAddress((void**)&pooled,g_pool); cudaGetSymbolAddress((void**)&hid,g_hid);

    f16 *hgh,*hgl,*qh,*ql,*kh,*kl,*vTh,*vTl,*Eh,*El,*xh,*xl;
    f16 *qrh,*qrl,*krh,*krl,*atth,*attl,*vTth,*vTtl,*oh,*ol,*ffh,*ffl,*plh,*pll,*sth,*stl;
    f16 *w0h,*w0l,*w1h,*w1l,*w2h,*w2l,*w3h,*w3l;
    cudaGetSymbolAddress((void**)&hgh,g_hg_h); cudaGetSymbolAddress((void**)&hgl,g_hg_l);
    cudaGetSymbolAddress((void**)&qh,g_q_h);   cudaGetSymbolAddress((void**)&ql,g_q_l);
    cudaGetSymbolAddress((void**)&kh,g_k_h);   cudaGetSymbolAddress((void**)&kl,g_k_l);
    cudaGetSymbolAddress((void**)&vTh,g_vT_h); cudaGetSymbolAddress((void**)&vTl,g_vT_l);
    cudaGetSymbolAddress((void**)&Eh,g_E_h);   cudaGetSymbolAddress((void**)&El,g_E_l);
    cudaGetSymbolAddress((void**)&xh,g_x_h);   cudaGetSymbolAddress((void**)&xl,g_x_l);
    cudaGetSymbolAddress((void**)&qrh,g_qr_h); cudaGetSymbolAddress((void**)&qrl,g_qr_l);
    cudaGetSymbolAddress((void**)&krh,g_kr_h); cudaGetSymbolAddress((void**)&krl,g_kr_l);
    cudaGetSymbolAddress((void**)&atth,g_att_h); cudaGetSymbolAddress((void**)&attl,g_att_l);
    cudaGetSymbolAddress((void**)&vTth,g_vTt_h); cudaGetSymbolAddress((void**)&vTtl,g_vTt_l);
    cudaGetSymbolAddress((void**)&oh,g_o_h);   cudaGetSymbolAddress((void**)&ol,g_o_l);
    cudaGetSymbolAddress((void**)&ffh,g_ff_h); cudaGetSymbolAddress((void**)&ffl,g_ff_l);
    cudaGetSymbolAddress((void**)&plh,g_pl_h); cudaGetSymbolAddress((void**)&pll,g_pl_l);
    cudaGetSymbolAddress((void**)&sth,g_st_h); cudaGetSymbolAddress((void**)&stl,g_st_l);
    cudaGetSymbolAddress((void**)&w0h,g_w0_h); cudaGetSymbolAddress((void**)&w0l,g_w0_l);
    cudaGetSymbolAddress((void**)&w1h,g_w1_h); cudaGetSymbolAddress((void**)&w1l,g_w1_l);
    cudaGetSymbolAddress((void**)&w2h,g_w2_h); cudaGetSymbolAddress((void**)&w2l,g_w2_l);
    cudaGetSymbolAddress((void**)&w3h,g_w3_h); cudaGetSymbolAddress((void**)&w3l,g_w3_l);

    const int M1 = BATCH*SE_;   // 16384
    const int MT = T_*BATCH;    // 32768

    build_hg_kernel<<<(T_*BATCH*SE_ + 255)/256, 256>>>(src, R_u, hg, hgh, hgl);

    // ---------------- prop layers ----------------
    for (int l = 0; l < 2; l++) {
        long wOff = (long)l*DFEAT*DFEAT;
        long bOff = (long)l*DFEAT;
        wsplit(p_Wq + wOff,    w0h, w0l, DFEAT*DFEAT);
        wsplit(p_Wk + wOff,    w1h, w1l, DFEAT*DFEAT);
        wsplit(p_Wv + wOff,    w2h, w2l, DFEAT*DFEAT);
        wsplit(p_Wskip + wOff, w3h, w3l, DFEAT*DFEAT);
        tgemm(hgh, hgl, DFEAT, 0,0, w0h, DFEAT, 0,0,
              0, qh, ql, DFEAT, 0,0, p_bq + bOff, 0, 1.f, 0, 1, 1, M1, DFEAT, DFEAT);
        tgemm(hgh, hgl, DFEAT, 0,0, w1h, DFEAT, 0,0,
              0, kh, kl, DFEAT, 0,0, p_bk + bOff, 0, 1.f, 0, 1, 1, M1, DFEAT, DFEAT);
        tgemm(hgh, hgl, DFEAT, 0,0, w2h, DFEAT, 0,0,
              v, 0, 0, DFEAT, 0,0, p_bv + bOff, 0, 1.f, 0, 1, 1, M1, DFEAT, DFEAT);
        tgemm(hgh, hgl, DFEAT, 0,0, w3h, DFEAT, 0,0,
              skip, 0, 0, DFEAT, 0,0, p_bskip + bOff, 0, 1.f, 0, 1, 1, M1, DFEAT, DFEAT);
        // scores[b] = q[b] @ k[b]^T / 32
        tgemm(qh, ql, DFEAT, (long)SE_*DFEAT, 0, kh, DFEAT, (long)SE_*DFEAT, 0,
              S, 0, 0, SE_, (long)SE_*SE_, 0, 0, 0, 0.03125f, 0, 1, BATCH,
              SE_, SE_, DFEAT);
        softmax_prop_kernel<<<BATCH*SE_, 128>>>(S, W, Eh, El, l > 0);
        convT_prop_kernel<<<dim3(DFEAT/32, SE_/32, BATCH), dim3(32,8)>>>(v, vTh, vTl);
        // hg = E @ vT^T + skip
        tgemm(Eh, El, SE_, (long)SE_*SE_, 0, vTh, SE_, (long)DFEAT*SE_, 0,
              hg, hgh, hgl, DFEAT, (long)SE_*DFEAT, 0, 0, skip, 1.f, 0, 1, BATCH,
              SE_, DFEAT, SE_);
    }

    build_x_kernel<<<(int)(((long)T_*BATCH*DMODEL + 255)/256), 256>>>(hg, times, x, xh, xl);

    const float attScale = 1.0f / sqrtf((float)HD);

    // ---------------- transformer layers ----------------
    for (int l = 0; l < 2; l++) {
        wsplit(t_Wqkv + (long)l*3*DMODEL*DMODEL, w0h, w0l, 3*DMODEL*DMODEL);
        wsplit(t_Wo   + (long)l*DMODEL*DMODEL,   w1h, w1l, DMODEL*DMODEL);
        wsplit(t_W1   + (long)l*DFF*DMODEL,      w2h, w2l, DFF*DMODEL);
        wsplit(t_W2   + (long)l*DMODEL*DFF,      w3h, w3l, DMODEL*DFF);

        tgemm(xh, xl, DMODEL, 0,0, w0h, DMODEL, 0,0,
              qkv, 0, 0, 3*DMODEL, 0,0, t_bqkv + (long)l*3*DMODEL, 0, 1.f, 0, 1, 1,
              MT, 3*DMODEL, DMODEL);
        repack_qk_kernel<<<(int)(((long)BATCH*NH*T_*DPAD + 255)/256), 256>>>(
            qkv, qrh, qrl, krh, krl);
        // att scores
        tgemm(qrh, qrl, DPAD, (long)T_*DPAD, 0, krh, DPAD, (long)T_*DPAD, 0,
              att, 0, 0, T_, (long)T_*T_, 0, 0, 0, attScale, 0, 1, BATCH*NH,
              T_, T_, DPAD);
        softmax_att_kernel<<<BATCH*NH*T_, 256>>>(att, lengths, atth, attl);
        convT_tran_kernel<<<dim3(T_/32, (HD+31)/32, BATCH*NH), dim3(32,8)>>>(qkv, vTth, vTtl);
        // o = att @ vTt^T  (split outputs only)
        tgemm(atth, attl, T_, (long)NH*T_*T_, (long)T_*T_,
              vTth, T_, (long)NH*HD*T_, (long)HD*T_,
              0, oh, ol, BATCH*DMODEL, DMODEL, HD,
              0, 0, 1.f, 0, NH, BATCH*NH, T_, HD, T_);
        // o2 = o @ Wo^T + bo (into qkv scratch)
        tgemm(oh, ol, DMODEL, 0,0, w1h, DMODEL, 0,0,
              qkv, 0, 0, DMODEL, 0,0, t_bo + (long)l*DMODEL, 0, 1.f, 0, 1, 1,
              MT, DMODEL, DMODEL);
        add_ln_kernel<<<MT, 256>>>(x, qkv, t_ln1g + (long)l*DMODEL,
                                   t_ln1b + (long)l*DMODEL, x, xh, xl);
        tgemm(xh, xl, DMODEL, 0,0, w2h, DMODEL, 0,0,
              0, ffh, ffl, DFF, 0,0, t_b1 + (long)l*DFF, 0, 1.f, 1, 1, 1,
              MT, DFF, DMODEL);
        tgemm(ffh, ffl, DFF, 0,0, w3h, DFF, 0,0,
              qkv, 0, 0, DMODEL, 0,0, t_b2 + (long)l*DMODEL, 0, 1.f, 0, 1, 1,
              MT, DMODEL, DFF);
        add_ln_kernel<<<MT, 256>>>(x, qkv, t_ln2g + (long)l*DMODEL,
                                   t_ln2b + (long)l*DMODEL, x, xh, xl);
    }

    // ---------------- head ----------------
    pool_kernel<<<dim3(BATCH, 4), 132>>>(x, lengths, pooled, plh, pll);
    wsplit(stat, sth, stl, BATCH*64);
    wsplit(static_W, w0h, w0l, 512*64);
    tgemm(sth, stl, 64, 0,0, w0h, 64, 0,0,
          0, plh + DMODEL, pll + DMODEL, DFINAL, 0,0,
          static_b, 0, 1.f, 0, 1, 1, BATCH, 512, 64);
    wsplit(mlp_W1, w1h, w1l, DFINAL*DFINAL);
    tgemm(plh, pll, DFINAL, 0,0, w1h, DFINAL, 0,0,
          hid, 0, 0, DFINAL, 0,0, mlp_b1, 0, 1.f, 1, 1, 1, BATCH, DFINAL, DFINAL);
    final_out_kernel<<<32, 256>>>(hid, mlp_W2, mlp_b2, out);
    (void)in_sizes; (void)n_in; (void)out_size;
}

// round 15
// speedup vs baseline: 1.4107x; 1.1264x over previous
#include <cuda_runtime.h>
#include <cuda_fp16.h>
#include <math.h>
#include <stdint.h>

typedef __half f16;

// ---------------- problem constants ----------------
constexpr int SE_    = 128;
constexpr int T_     = 256;
constexpr int BATCH  = 128;
constexpr int NH     = 4;
constexpr int DFF    = 128;
constexpr int DFEAT  = 1024;
constexpr int DMODEL = 528;
constexpr int DFINAL = 1040;
constexpr int HD     = 132;
constexpr int DPAD   = 136;               // HD padded to 16B-aligned rows
constexpr int LDQ    = BATCH*3*DMODEL;    // 202752

// ---------------- fp32 scratch ----------------
__device__ float g_hg  [(size_t)BATCH*SE_*DFEAT];
__device__ float g_v   [(size_t)BATCH*SE_*DFEAT];
__device__ float g_skip[(size_t)BATCH*SE_*DFEAT];
__device__ float g_S   [(size_t)BATCH*SE_*SE_];
__device__ float g_W   [(size_t)BATCH*SE_*SE_];
__device__ float g_x   [(size_t)T_*BATCH*DMODEL];
__device__ float g_qkv [(size_t)T_*BATCH*3*DMODEL];
__device__ float g_att [(size_t)BATCH*NH*T_*T_];
__device__ float g_pool[(size_t)BATCH*DFINAL];
__device__ float g_hid [(size_t)BATCH*DFINAL];

// ---------------- fp16 hi/lo split scratch ----------------
__device__ f16 g_hg_h [(size_t)BATCH*SE_*DFEAT];
__device__ f16 g_hg_l [(size_t)BATCH*SE_*DFEAT];
__device__ f16 g_q_h  [(size_t)BATCH*SE_*DFEAT];
__device__ f16 g_q_l  [(size_t)BATCH*SE_*DFEAT];
__device__ f16 g_k_h  [(size_t)BATCH*SE_*DFEAT];
__device__ f16 g_k_l  [(size_t)BATCH*SE_*DFEAT];
__device__ f16 g_vT_h [(size_t)BATCH*DFEAT*SE_];
__device__ f16 g_vT_l [(size_t)BATCH*DFEAT*SE_];
__device__ f16 g_E_h  [(size_t)BATCH*SE_*SE_];
__device__ f16 g_E_l  [(size_t)BATCH*SE_*SE_];
__device__ f16 g_x_h  [(size_t)T_*BATCH*DMODEL];
__device__ f16 g_x_l  [(size_t)T_*BATCH*DMODEL];
__device__ f16 g_qr_h [(size_t)BATCH*NH*T_*DPAD];
__device__ f16 g_qr_l [(size_t)BATCH*NH*T_*DPAD];
__device__ f16 g_kr_h [(size_t)BATCH*NH*T_*DPAD];
__device__ f16 g_kr_l [(size_t)BATCH*NH*T_*DPAD];
__device__ f16 g_att_h[(size_t)BATCH*NH*T_*T_];
__device__ f16 g_att_l[(size_t)BATCH*NH*T_*T_];
__device__ f16 g_vTt_h[(size_t)BATCH*NH*HD*T_];
__device__ f16 g_vTt_l[(size_t)BATCH*NH*HD*T_];
__device__ f16 g_o_h  [(size_t)T_*BATCH*DMODEL];
__device__ f16 g_o_l  [(size_t)T_*BATCH*DMODEL];
__device__ f16 g_ff_h [(size_t)T_*BATCH*DFF];
__device__ f16 g_ff_l [(size_t)T_*BATCH*DFF];
__device__ f16 g_pl_h [(size_t)BATCH*DFINAL];
__device__ f16 g_pl_l [(size_t)BATCH*DFINAL];
__device__ f16 g_st_h [(size_t)BATCH*64];
__device__ f16 g_st_l [(size_t)BATCH*64];
constexpr size_t WBN = 1081600;   // >= mlp_W1 (1040*1040), >= Wqkv slice
__device__ f16 g_w0_h[WBN]; __device__ f16 g_w0_l[WBN];
__device__ f16 g_w1_h[WBN]; __device__ f16 g_w1_l[WBN];
__device__ f16 g_w2_h[WBN]; __device__ f16 g_w2_l[WBN];
__device__ f16 g_w3_h[WBN]; __device__ f16 g_w3_l[WBN];

// ---------------- helpers ----------------
__device__ __forceinline__ void split1(float v, f16& h, f16& l) {
    h = __float2half_rn(v);
    l = __float2half_rn(v - __half2float(h));
}
__device__ __forceinline__ uint32_t smem_u32(const void* p) {
    uint32_t a;
    asm("{ .reg .u64 t; cvta.to.shared.u64 t, %1; cvt.u32.u64 %0, t; }" : "=r"(a) : "l"(p));
    return a;
}
__device__ __forceinline__ void mma_f16(float* d, const uint32_t* a, const uint32_t* b) {
    asm("mma.sync.aligned.m16n8k16.row.col.f32.f16.f16.f32 "
        "{%0,%1,%2,%3}, {%4,%5,%6,%7}, {%8,%9}, {%0,%1,%2,%3};"
        : "+f"(d[0]), "+f"(d[1]), "+f"(d[2]), "+f"(d[3])
        : "r"(a[0]), "r"(a[1]), "r"(a[2]), "r"(a[3]), "r"(b[0]), "r"(b[1]));
}
#define LDSM4(r0,r1,r2,r3,addr) \
    asm volatile("ldmatrix.sync.aligned.m8n8.x4.shared.b16 {%0,%1,%2,%3}, [%4];" \
        : "=r"(r0), "=r"(r1), "=r"(r2), "=r"(r3) : "r"(addr))
#define CPASYNC(dst, src, zf) \
    asm volatile("cp.async.cg.shared.global [%0], [%1], 16, %2;" \
        :: "r"(dst), "l"(src), "r"(zf) : "memory")

// =====================================================================
// HMMA 2xFP16 NT GEMM on pre-split operands.
// acc += Ah*Bh + Al*Bh. Block tile 128x128, K-chunk 32, 3-stage cp.async,
// ldmatrix, pitch-80 smem (R8-verified conflict-free layout).
// __launch_bounds__(256,2): 2 CTAs/SM -> 4 warps/SMSP for the arbiter.
// =====================================================================
constexpr int TGP = 80;        // bytes per smem row
constexpr int TGT = 128*TGP;   // 10240 bytes per tile
constexpr int TGB = 3*TGT;     // Ah, Al, Bh = 30720
constexpr int TGS = 3*TGB;     // 92160 bytes (3 stages) -> 2 CTAs fit

__global__ __launch_bounds__(256, 2) void tgemm_kernel(
    const f16* __restrict__ Ah, const f16* __restrict__ Al, int lda, long sA1, long sA2,
    const f16* __restrict__ Bh, int ldb, long sB1, long sB2,
    float* __restrict__ C, f16* __restrict__ Ch, f16* __restrict__ Cl,
    int ldc, long sC1, long sC2,
    const float* __restrict__ bias, const float* __restrict__ addend,
    float scale, int doRelu, int zdiv, int M, int N, int K)
{
    extern __shared__ char smraw[];
    uint32_t sb = smem_u32(smraw);
    int tid = threadIdx.x, wid = tid >> 5, lane = tid & 31;
    int wm = wid & 3, wn = wid >> 2;
    int g = lane >> 2, t4 = lane & 3;

    int z = blockIdx.z, z1 = z / zdiv, z2 = z % zdiv;
    const f16* A_h = Ah + z1*sA1 + z2*sA2;
    const f16* A_l = Al + z1*sA1 + z2*sA2;
    const f16* B_h = Bh + z1*sB1 + z2*sB2;
    float* Cb = C ? C + z1*sC1 + z2*sC2 : (float*)0;
    f16* Chb = Ch ? Ch + z1*sC1 + z2*sC2 : (f16*)0;
    f16* Clb = Cl ? Cl + z1*sC1 + z2*sC2 : (f16*)0;
    const float* Db = addend ? addend + z1*sC1 + z2*sC2 : (const float*)0;

    int bm0 = blockIdx.y * 128;
    int bn0 = blockIdx.x * 128;
    int nk = (K + 31) >> 5;

    auto issue = [&](int c, int buf) {
        int k0 = c << 5;
        uint32_t bb = sb + (uint32_t)buf * TGB;
        #pragma unroll
        for (int j = 0; j < 6; j++) {
            int u = tid + j * 256;          // 0..1535
            int tile = j >> 1;              // 0:Ah 1:Al 2:Bh (compile-time)
            int within = u & 511;
            int rr = within >> 2, c4 = within & 3;
            int gk = k0 + c4 * 8;
            int zf = 2 * (K - gk); zf = zf < 0 ? 0 : (zf > 16 ? 16 : zf);
            uint32_t sa = bb + (uint32_t)tile*TGT + rr * TGP + c4 * 16;
            if (tile == 0) {
                int m = bm0 + rr;
                int z8 = (m < M) ? zf : 0;
                const f16* p = z8 ? (A_h + (long)m * lda + gk) : A_h;
                CPASYNC(sa, p, z8);
            } else if (tile == 1) {
                int m = bm0 + rr;
                int z8 = (m < M) ? zf : 0;
                const f16* p = z8 ? (A_l + (long)m * lda + gk) : A_l;
                CPASYNC(sa, p, z8);
            } else {
                int n = bn0 + rr;
                int z8 = (n < N) ? zf : 0;
                const f16* p = z8 ? (B_h + (long)n * ldb + gk) : B_h;
                CPASYNC(sa, p, z8);
            }
        }
        asm volatile("cp.async.commit_group;" ::: "memory");
    };

    issue(0, 0);
    if (nk > 1) issue(1, 1);

    float acc[2][8][4];
    #pragma unroll
    for (int i = 0; i < 2; i++)
        #pragma unroll
        for (int j = 0; j < 8; j++)
            #pragma unroll
            for (int d = 0; d < 4; d++) acc[i][j][d] = 0.f;

    int aRow  = wm*32 + (lane & 7) + ((lane >> 3) & 1) * 8;
    int aColB = (lane >> 4) * 16;
    int bRow  = wn*64 + (lane & 7) + (lane >> 4) * 8;
    int bColB = ((lane >> 3) & 1) * 16;

    for (int c = 0; c < nk; c++) {
        if (c + 1 < nk) asm volatile("cp.async.wait_group 1;" ::: "memory");
        else            asm volatile("cp.async.wait_group 0;" ::: "memory");
        __syncthreads();
        if (c + 2 < nk) issue(c + 2, (c + 2) % 3);

        uint32_t bb = sb + (uint32_t)(c % 3) * TGB;
        uint32_t aH = bb + aRow * TGP + aColB;
        uint32_t aL = aH + TGT;
        uint32_t bH = bb + 2*TGT + bRow * TGP + bColB;

        int smax = (K - (c << 5) + 15) >> 4;
        if (smax > 2) smax = 2;
        #pragma unroll 2
        for (int s = 0; s < smax; s++) {
            uint32_t ah[2][4], al[2][4], bh[8][2];
            #pragma unroll
            for (int mt = 0; mt < 2; mt++) {
                LDSM4(ah[mt][0], ah[mt][1], ah[mt][2], ah[mt][3], aH + mt*(16*TGP) + s*32);
                LDSM4(al[mt][0], al[mt][1], al[mt][2], al[mt][3], aL + mt*(16*TGP) + s*32);
            }
            #pragma unroll
            for (int p = 0; p < 4; p++) {
                LDSM4(bh[2*p][0], bh[2*p][1], bh[2*p+1][0], bh[2*p+1][1], bH + p*(16*TGP) + s*32);
            }
            #pragma unroll
            for (int mt = 0; mt < 2; mt++)
                #pragma unroll
                for (int nt = 0; nt < 8; nt++)
                    mma_f16(acc[mt][nt], ah[mt], bh[nt]);
            #pragma unroll
            for (int mt = 0; mt < 2; mt++)
                #pragma unroll
                for (int nt = 0; nt < 8; nt++)
                    mma_f16(acc[mt][nt], al[mt], bh[nt]);
        }
    }

    // epilogue
    #pragma unroll
    for (int mt = 0; mt < 2; mt++) {
        int rlo = bm0 + wm*32 + mt*16 + g;
        int rhi = rlo + 8;
        #pragma unroll
        for (int nt = 0; nt < 8; nt++) {
            int c0 = bn0 + wn*64 + nt*8 + t4*2;
            #pragma unroll
            for (int hh = 0; hh < 2; hh++) {
                int row = hh ? rhi : rlo;
                if (row >= M) continue;
                #pragma unroll
                for (int cc = 0; cc < 2; cc++) {
                    int n = c0 + cc;
                    if (n >= N) continue;
                    long ci = (long)row * ldc + n;
                    float vv = acc[mt][nt][hh*2 + cc] * scale;
                    if (bias) vv += __ldg(bias + n);
                    if (Db)   vv += Db[ci];
                    if (doRelu) vv = fmaxf(vv, 0.f);
                    if (Cb) Cb[ci] = vv;
                    if (Chb) { f16 h, l; split1(vv, h, l); Chb[ci] = h; Clb[ci] = l; }
                }
            }
        }
    }
}

// ---------------- converts / repacks ----------------
__global__ void split_kernel(const float* __restrict__ in,
                             f16* __restrict__ h, f16* __restrict__ l, int n)
{
    int i = blockIdx.x * 256 + threadIdx.x;
    if (i < n) { f16 hv, lv; split1(in[i], hv, lv); h[i] = hv; l[i] = lv; }
}

// prop v [b][se][feat] -> vT [b][feat][se], split
__global__ void convT_prop_kernel(const float* __restrict__ v,
                                  f16* __restrict__ th, f16* __restrict__ tl)
{
    __shared__ float tile[32][33];
    int b = blockIdx.z;
    int f0 = blockIdx.x * 32, s0 = blockIdx.y * 32;
    int tx = threadIdx.x, ty = threadIdx.y;   // 32 x 8
    const float* vb = v + (long)b*SE_*DFEAT;
    #pragma unroll
    for (int k2 = 0; k2 < 4; k2++)
        tile[ty + k2*8][tx] = vb[(long)(s0 + ty + k2*8)*DFEAT + f0 + tx];
    __syncthreads();
    f16* thb = th + (long)b*DFEAT*SE_;
    f16* tlb = tl + (long)b*DFEAT*SE_;
    #pragma unroll
    for (int k2 = 0; k2 < 4; k2++) {
        float val = tile[tx][ty + k2*8];
        long oi = (long)(f0 + ty + k2*8)*SE_ + s0 + tx;
        f16 h, l; split1(val, h, l); thb[oi] = h; tlb[oi] = l;
    }
}

// tran v slice of qkv -> vTt [bh][d][t], split
__global__ void convT_tran_kernel(const float* __restrict__ qkv,
                                  f16* __restrict__ th, f16* __restrict__ tl)
{
    __shared__ float tile[32][33];
    int bh = blockIdx.z; int b = bh >> 2, h = bh & 3;
    int t0 = blockIdx.x * 32, d0 = blockIdx.y * 32;
    int tx = threadIdx.x, ty = threadIdx.y;   // 32 x 8
    const float* base = qkv + (long)b*3*DMODEL + 2*DMODEL + h*HD;
    #pragma unroll
    for (int k2 = 0; k2 < 4; k2++) {
        int d = d0 + tx;
        tile[ty + k2*8][tx] = (d < HD) ? base[(long)(t0 + ty + k2*8)*LDQ + d] : 0.f;
    }
    __syncthreads();
    f16* thb = th + (long)bh*HD*T_;
    f16* tlb = tl + (long)bh*HD*T_;
    #pragma unroll
    for (int k2 = 0; k2 < 4; k2++) {
        int d = d0 + ty + k2*8;
        if (d < HD) {
            float val = tile[tx][ty + k2*8];
            long oi = (long)d*T_ + t0 + tx;
            f16 hh, ll; split1(val, hh, ll); thb[oi] = hh; tlb[oi] = ll;
        }
    }
}

// q,k parts of qkv -> [bh][t][DPAD] split (zero-pad 132->136)
__global__ void repack_qk_kernel(const float* __restrict__ qkv,
                                 f16* __restrict__ qh, f16* __restrict__ ql,
                                 f16* __restrict__ kh, f16* __restrict__ kl)
{
    long idx = (long)blockIdx.x * 256 + threadIdx.x;
    if (idx >= (long)BATCH*NH*T_*DPAD) return;
    int d = (int)(idx % DPAD);
    long r = idx / DPAD;
    int t = (int)(r % T_);
    int bh = (int)(r / T_);
    int b = bh >> 2, h = bh & 3;
    long src = (long)t*LDQ + (long)b*3*DMODEL + h*HD;
    float qv = (d < HD) ? qkv[src + d] : 0.f;
    float kv = (d < HD) ? qkv[src + DMODEL + d] : 0.f;
    f16 hh, ll;
    split1(qv, hh, ll); qh[idx] = hh; ql[idx] = ll;
    split1(kv, hh, ll); kh[idx] = hh; kl[idx] = ll;
}

// ---------------- elementwise / reduction kernels ---------------------------
__global__ void build_hg_kernel(const float* __restrict__ src,
                                const float* __restrict__ R_u,
                                float* __restrict__ hg,
                                f16* __restrict__ hh, f16* __restrict__ hl)
{
    int idx = blockIdx.x * blockDim.x + threadIdx.x;
    if (idx >= T_*BATCH*SE_) return;
    int se = idx % SE_;
    int tb = idx / SE_;
    int b = tb % BATCH;
    int t = tb / BATCH;
    float s = src[(long)t*BATCH*2*SE_ + (long)b*2*SE_ + se];
    long base = (long)b*SE_*DFEAT + (long)se*DFEAT + t*4;
    #pragma unroll
    for (int d = 0; d < 4; d++) {
        float v = fmaxf(s * R_u[se*4 + d], 0.f);
        hg[base + d] = v;
        f16 h, l; split1(v, h, l); hh[base + d] = h; hl[base + d] = l;
    }
}

__global__ __launch_bounds__(128) void softmax_prop_kernel(
    float* __restrict__ S, float* __restrict__ W,
    f16* __restrict__ Eh, f16* __restrict__ El, int useW)
{
    int row = blockIdx.x;
    float* sr = S + (long)row*SE_;
    float* wr = W + (long)row*SE_;
    int tid = threadIdx.x;
    float v = sr[tid];
    __shared__ float red[4];
    float m = v;
    #pragma unroll
    for (int o = 16; o > 0; o >>= 1) m = fmaxf(m, __shfl_xor_sync(0xffffffffu, m, o));
    if ((tid & 31) == 0) red[tid >> 5] = m;
    __syncthreads();
    m = fmaxf(fmaxf(red[0], red[1]), fmaxf(red[2], red[3]));
    float e = expf(v - m);
    float s = e;
    #pragma unroll
    for (int o = 16; o > 0; o >>= 1) s += __shfl_xor_sync(0xffffffffu, s, o);
    __syncthreads();
    if ((tid & 31) == 0) red[tid >> 5] = s;
    __syncthreads();
    s = red[0] + red[1] + red[2] + red[3];
    float alpha = e / s;
    float wprev = useW ? wr[tid] : 1.0f;
    float E = alpha * wprev;
    f16 h, l; split1(E, h, l);
    Eh[(long)row*SE_ + tid] = h;
    El[(long)row*SE_ + tid] = l;
    wr[tid] = alpha;
}

__global__ void build_x_kernel(const float* __restrict__ hg,
                               const float* __restrict__ times,
                               float* __restrict__ x,
                               f16* __restrict__ xh, f16* __restrict__ xl)
{
    long idx = (long)blockIdx.x * blockDim.x + threadIdx.x;
    if (idx >= (long)T_*BATCH*DMODEL) return;
    int c = (int)(idx % DMODEL);
    long tb = idx / DMODEL;
    int b = (int)(tb % BATCH);
    int t = (int)(tb / BATCH);
    float v;
    if (c < 512) {
        int se = c >> 2, d = c & 3;
        v = hg[(long)b*SE_*DFEAT + (long)se*DFEAT + t*4 + d];
    } else {
        int i = c - 512;
        int ii = (i < 8) ? i : i - 8;
        float tsv = powf(256.0f, (float)ii * (1.0f/7.0f));
        float st = times[(long)t*BATCH + b] / tsv;
        v = (i < 8) ? sinf(st) : cosf(st);
    }
    x[idx] = v;
    f16 h, l; split1(v, h, l); xh[idx] = h; xl[idx] = l;
}

__global__ __launch_bounds__(256) void softmax_att_kernel(
    const float* __restrict__ S, const int* __restrict__ lengths,
    f16* __restrict__ Ah, f16* __restrict__ Alo)
{
    int row = blockIdx.x;
    int b = row >> 10;
    int len = lengths[b];
    const float* sr = S + (long)row*T_;
    int tid = threadIdx.x;
    float v = (tid < len) ? sr[tid] : -1e9f;
    __shared__ float red[8];
    float m = v;
    #pragma unroll
    for (int o = 16; o > 0; o >>= 1) m = fmaxf(m, __shfl_xor_sync(0xffffffffu, m, o));
    if ((tid & 31) == 0) red[tid >> 5] = m;
    __syncthreads();
    m = red[0];
    #pragma unroll
    for (int i = 1; i < 8; i++) m = fmaxf(m, red[i]);
    float e = expf(v - m);
    float s = e;
    #pragma unroll
    for (int o = 16; o > 0; o >>= 1) s += __shfl_xor_sync(0xffffffffu, s, o);
    __syncthreads();
    if ((tid & 31) == 0) red[tid >> 5] = s;
    __syncthreads();
    s = 0.f;
    #pragma unroll
    for (int i = 0; i < 8; i++) s += red[i];
    float a = e / s;
    f16 h, l; split1(a, h, l);
    Ah[(long)row*T_ + tid] = h;
    Alo[(long)row*T_ + tid] = l;
}

// Vectorized: 256 threads, thread t handles cols {2t, 2t+1}; t<8 also {512+2t, 513+2t}.
__global__ __launch_bounds__(256) void add_ln_kernel(
    const float* __restrict__ xin, const float* __restrict__ res,
    const float* __restrict__ g, const float* __restrict__ be,
    float* __restrict__ out, f16* __restrict__ oh, f16* __restrict__ ol)
{
    int row = blockIdx.x;
    const float2* xr = (const float2*)(xin + (long)row*DMODEL);
    const float2* rr = (const float2*)(res + (long)row*DMODEL);
    float2* orow = (float2*)(out + (long)row*DMODEL);
    __half2* ohrow = (__half2*)(oh + (long)row*DMODEL);
    __half2* olrow = (__half2*)(ol + (long)row*DMODEL);
    int tid = threadIdx.x;
    int lane = tid & 31, wrp = tid >> 5;
    __shared__ float red[8];

    float2 a = xr[tid], b = rr[tid];
    float2 v0 = make_float2(a.x + b.x, a.y + b.y);
    float2 v1 = make_float2(0.f, 0.f);
    bool extra = tid < 8;
    if (extra) {
        float2 a2 = xr[256 + tid], b2 = rr[256 + tid];
        v1 = make_float2(a2.x + b2.x, a2.y + b2.y);
    }
    float s = v0.x + v0.y + v1.x + v1.y;
    #pragma unroll
    for (int o = 16; o > 0; o >>= 1) s += __shfl_xor_sync(0xffffffffu, s, o);
    if (lane == 0) red[wrp] = s;
    __syncthreads();
    s = 0.f;
    #pragma unroll
    for (int i = 0; i < 8; i++) s += red[i];
    float mean = s * (1.0f/DMODEL);
    __syncthreads();

    float d0x = v0.x - mean, d0y = v0.y - mean;
    float vs = d0x*d0x + d0y*d0y;
    if (extra) { float d1x = v1.x - mean, d1y = v1.y - mean; vs += d1x*d1x + d1y*d1y; }
    #pragma unroll
    for (int o = 16; o > 0; o >>= 1) vs += __shfl_xor_sync(0xffffffffu, vs, o);
    if (lane == 0) red[wrp] = vs;
    __syncthreads();
    vs = 0.f;
    #pragma unroll
    for (int i = 0; i < 8; i++) vs += red[i];
    float rstd = rsqrtf(vs * (1.0f/DMODEL) + 1e-5f);

    {
        int c = 2*tid;
        float o0 = (v0.x - mean) * rstd * __ldg(g + c)     + __ldg(be + c);
        float o1 = (v0.y - mean) * rstd * __ldg(g + c + 1) + __ldg(be + c + 1);
        orow[tid] = make_float2(o0, o1);
        f16 h0, l0, h1, l1;
        split1(o0, h0, l0); split1(o1, h1, l1);
        ohrow[tid] = __halves2half2(h0, h1);
        olrow[tid] = __halves2half2(l0, l1);
    }
    if (extra) {
        int c = 512 + 2*tid;
        float o0 = (v1.x - mean) * rstd * __ldg(g + c)     + __ldg(be + c);
        float o1 = (v1.y - mean) * rstd * __ldg(g + c + 1) + __ldg(be + c + 1);
        orow[256 + tid] = make_float2(o0, o1);
        f16 h0, l0, h1, l1;
        split1(o0, h0, l0); split1(o1, h1, l1);
        ohrow[256 + tid] = __halves2half2(h0, h1);
        olrow[256 + tid] = __halves2half2(l0, l1);
    }
}

__global__ void pool_kernel(const float* __restrict__ x,
                            const int* __restrict__ lengths,
                            float* __restrict__ pooled,
                            f16* __restrict__ ph, f16* __restrict__ pl)
{
    int b = blockIdx.x;
    int c = blockIdx.y * 132 + threadIdx.x;
    if (threadIdx.x >= 132 || c >= DMODEL) return;
    int len = lengths[b];
    float s = 0.f;
    for (int t = 0; t < len; t++)
        s += x[(long)t*BATCH*DMODEL + (long)b*DMODEL + c];
    float v = s / ((float)len + 1.0f);
    long oi = (long)b*DFINAL + c;
    pooled[oi] = v;
    f16 h, l; split1(v, h, l); ph[oi] = h; pl[oi] = l;
}

__global__ __launch_bounds__(256) void final_out_kernel(
    const float* __restrict__ hid, const float* __restrict__ W2,
    const float* __restrict__ b2, float* __restrict__ out)
{
    int p = blockIdx.x * 8 + (threadIdx.x >> 5);
    if (p >= BATCH*2) return;
    int b = p >> 1, c = p & 1;
    int lane = threadIdx.x & 31;
    float s = 0.f;
    for (int k = lane; k < DFINAL; k += 32)
        s += hid[(long)b*DFINAL + k] * W2[(long)c*DFINAL + k];
    #pragma unroll
    for (int o = 16; o > 0; o >>= 1) s += __shfl_xor_sync(0xffffffffu, s, o);
    if (lane == 0) out[p] = s + b2[c];
}

// ---------------- host helpers ----------------
static void tgemm(const f16* Ah, const f16* Al, int lda, long sA1, long sA2,
                  const f16* Bh, int ldb, long sB1, long sB2,
                  float* C, f16* Ch, f16* Cl, int ldc, long sC1, long sC2,
                  const float* bias, const float* add, float scale, int relu,
                  int zdiv, int nz, int M, int N, int K)
{
    dim3 grid((N+127)/128, (M+127)/128, nz);
    tgemm_kernel<<<grid, 256, TGS>>>(Ah, Al, lda, sA1, sA2, Bh, ldb, sB1, sB2,
                                     C, Ch, Cl, ldc, sC1, sC2, bias, add, scale,
                                     relu, zdiv, M, N, K);
}
static void wsplit(const float* in, f16* h, f16* l, int n) {
    split_kernel<<<(n+255)/256, 256>>>(in, h, l, n);
}

extern "C" void kernel_launch(void* const* d_in, const int* in_sizes, int n_in,
                              void* d_out, int out_size)
{
    const float* src      = (const float*)d_in[0];
    const float* times    = (const float*)d_in[1];
    const int*   lengths  = (const int*)  d_in[2];
    const float* stat     = (const float*)d_in[3];
    const float* R_u      = (const float*)d_in[4];
    const float* static_W = (const float*)d_in[5];
    const float* static_b = (const float*)d_in[6];
    const float* p_Wq     = (const float*)d_in[7];
    const float* p_Wk     = (const float*)d_in[8];
    const float* p_Wv     = (const float*)d_in[9];
    const float* p_bq     = (const float*)d_in[10];
    const float* p_bk     = (const float*)d_in[11];
    const float* p_bv     = (const float*)d_in[12];
    const float* p_Wskip  = (const float*)d_in[13];
    const float* p_bskip  = (const float*)d_in[14];
    const float* t_Wqkv   = (const float*)d_in[15];
    const float* t_bqkv   = (const float*)d_in[16];
    const float* t_Wo     = (const float*)d_in[17];
    const float* t_bo     = (const float*)d_in[18];
    const float* t_W1     = (const float*)d_in[19];
    const float* t_b1     = (const float*)d_in[20];
    const float* t_W2     = (const float*)d_in[21];
    const float* t_b2     = (const float*)d_in[22];
    const float* t_ln1g   = (const float*)d_in[23];
    const float* t_ln1b   = (const float*)d_in[24];
    const float* t_ln2g   = (const float*)d_in[25];
    const float* t_ln2b   = (const float*)d_in[26];
    const float* mlp_W1   = (const float*)d_in[27];
    const float* mlp_b1   = (const float*)d_in[28];
    const float* mlp_W2   = (const float*)d_in[29];
    const float* mlp_b2   = (const float*)d_in[30];
    float* out = (float*)d_out;

    cudaFuncSetAttribute(tgemm_kernel, cudaFuncAttributeMaxDynamicSharedMemorySize, TGS);

    float *hg,*v,*skip,*S,*W,*x,*qkv,*att,*pooled,*hid;
    cudaGetSymbolAddress((void**)&hg,g_hg);
    cudaGetSymbolAddress((void**)&v,g_v);
    cudaGetSymbolAddress((void**)&skip,g_skip); cudaGetSymbolAddress((void**)&S,g_S);
    cudaGetSymbolAddress((void**)&W,g_W);   cudaGetSymbolAddress((void**)&x,g_x);
    cudaGetSymbolAddress((void**)&qkv,g_qkv); cudaGetSymbolAddress((void**)&att,g_att);
    cudaGetSymbolAddress((void**)&pooled,g_pool); cudaGetSymbolAddress((void**)&hid,g_hid);

    f16 *hgh,*hgl,*qh,*ql,*kh,*kl,*vTh,*vTl,*Eh,*El,*xh,*xl;
    f16 *qrh,*qrl,*krh,*krl,*atth,*attl,*vTth,*vTtl,*oh,*ol,*ffh,*ffl,*plh,*pll,*sth,*stl;
    f16 *w0h,*w0l,*w1h,*w1l,*w2h,*w2l,*w3h,*w3l;
    cudaGetSymbolAddress((void**)&hgh,g_hg_h); cudaGetSymbolAddress((void**)&hgl,g_hg_l);
    cudaGetSymbolAddress((void**)&qh,g_q_h);   cudaGetSymbolAddress((void**)&ql,g_q_l);
    cudaGetSymbolAddress((void**)&kh,g_k_h);   cudaGetSymbolAddress((void**)&kl,g_k_l);
    cudaGetSymbolAddress((void**)&vTh,g_vT_h); cudaGetSymbolAddress((void**)&vTl,g_vT_l);
    cudaGetSymbolAddress((void**)&Eh,g_E_h);   cudaGetSymbolAddress((void**)&El,g_E_l);
    cudaGetSymbolAddress((void**)&xh,g_x_h);   cudaGetSymbolAddress((void**)&xl,g_x_l);
    cudaGetSymbolAddress((void**)&qrh,g_qr_h); cudaGetSymbolAddress((void**)&qrl,g_qr_l);
    cudaGetSymbolAddress((void**)&krh,g_kr_h); cudaGetSymbolAddress((void**)&krl,g_kr_l);
    cudaGetSymbolAddress((void**)&atth,g_att_h); cudaGetSymbolAddress((void**)&attl,g_att_l);
    cudaGetSymbolAddress((void**)&vTth,g_vTt_h); cudaGetSymbolAddress((void**)&vTtl,g_vTt_l);
    cudaGetSymbolAddress((void**)&oh,g_o_h);   cudaGetSymbolAddress((void**)&ol,g_o_l);
    cudaGetSymbolAddress((void**)&ffh,g_ff_h); cudaGetSymbolAddress((void**)&ffl,g_ff_l);
    cudaGetSymbolAddress((void**)&plh,g_pl_h); cudaGetSymbolAddress((void**)&pll,g_pl_l);
    cudaGetSymbolAddress((void**)&sth,g_st_h); cudaGetSymbolAddress((void**)&stl,g_st_l);
    cudaGetSymbolAddress((void**)&w0h,g_w0_h); cudaGetSymbolAddress((void**)&w0l,g_w0_l);
    cudaGetSymbolAddress((void**)&w1h,g_w1_h); cudaGetSymbolAddress((void**)&w1l,g_w1_l);
    cudaGetSymbolAddress((void**)&w2h,g_w2_h); cudaGetSymbolAddress((void**)&w2l,g_w2_l);
    cudaGetSymbolAddress((void**)&w3h,g_w3_h); cudaGetSymbolAddress((void**)&w3l,g_w3_l);

    const int M1 = BATCH*SE_;   // 16384
    const int MT = T_*BATCH;    // 32768

    build_hg_kernel<<<(T_*BATCH*SE_ + 255)/256, 256>>>(src, R_u, hg, hgh, hgl);

    // ---------------- prop layers ----------------
    for (int l = 0; l < 2; l++) {
        long wOff = (long)l*DFEAT*DFEAT;
        long bOff = (long)l*DFEAT;
        wsplit(p_Wq + wOff,    w0h, w0l, DFEAT*DFEAT);
        wsplit(p_Wk + wOff,    w1h, w1l, DFEAT*DFEAT);
        wsplit(p_Wv + wOff,    w2h, w2l, DFEAT*DFEAT);
        wsplit(p_Wskip + wOff, w3h, w3l, DFEAT*DFEAT);
        tgemm(hgh, hgl, DFEAT, 0,0, w0h, DFEAT, 0,0,
              0, qh, ql, DFEAT, 0,0, p_bq + bOff, 0, 1.f, 0, 1, 1, M1, DFEAT, DFEAT);
        tgemm(hgh, hgl, DFEAT, 0,0, w1h, DFEAT, 0,0,
              0, kh, kl, DFEAT, 0,0, p_bk + bOff, 0, 1.f, 0, 1, 1, M1, DFEAT, DFEAT);
        tgemm(hgh, hgl, DFEAT, 0,0, w2h, DFEAT, 0,0,
              v, 0, 0, DFEAT, 0,0, p_bv + bOff, 0, 1.f, 0, 1, 1, M1, DFEAT, DFEAT);
        tgemm(hgh, hgl, DFEAT, 0,0, w3h, DFEAT, 0,0,
              skip, 0, 0, DFEAT, 0,0, p_bskip + bOff, 0, 1.f, 0, 1, 1, M1, DFEAT, DFEAT);
        // scores[b] = q[b] @ k[b]^T / 32
        tgemm(qh, ql, DFEAT, (long)SE_*DFEAT, 0, kh, DFEAT, (long)SE_*DFEAT, 0,
              S, 0, 0, SE_, (long)SE_*SE_, 0, 0, 0, 0.03125f, 0, 1, BATCH,
              SE_, SE_, DFEAT);
        softmax_prop_kernel<<<BATCH*SE_, 128>>>(S, W, Eh, El, l > 0);
        convT_prop_kernel<<<dim3(DFEAT/32, SE_/32, BATCH), dim3(32,8)>>>(v, vTh, vTl);
        // hg = E @ vT^T + skip
        tgemm(Eh, El, SE_, (long)SE_*SE_, 0, vTh, SE_, (long)DFEAT*SE_, 0,
              hg, hgh, hgl, DFEAT, (long)SE_*DFEAT, 0, 0, skip, 1.f, 0, 1, BATCH,
              SE_, DFEAT, SE_);
    }

    build_x_kernel<<<(int)(((long)T_*BATCH*DMODEL + 255)/256), 256>>>(hg, times, x, xh, xl);

    const float attScale = 1.0f / sqrtf((float)HD);

    // ---------------- transformer layers ----------------
    for (int l = 0; l < 2; l++) {
        wsplit(t_Wqkv + (long)l*3*DMODEL*DMODEL, w0h, w0l, 3*DMODEL*DMODEL);
        wsplit(t_Wo   + (long)l*DMODEL*DMODEL,   w1h, w1l, DMODEL*DMODEL);
        wsplit(t_W1   + (long)l*DFF*DMODEL,      w2h, w2l, DFF*DMODEL);
        wsplit(t_W2   + (long)l*DMODEL*DFF,      w3h, w3l, DMODEL*DFF);

        tgemm(xh, xl, DMODEL, 0,0, w0h, DMODEL, 0,0,
              qkv, 0, 0, 3*DMODEL, 0,0, t_bqkv + (long)l*3*DMODEL, 0, 1.f, 0, 1, 1,
              MT, 3*DMODEL, DMODEL);
        repack_qk_kernel<<<(int)(((long)BATCH*NH*T_*DPAD + 255)/256), 256>>>(
            qkv, qrh, qrl, krh, krl);
        // att scores
        tgemm(qrh, qrl, DPAD, (long)T_*DPAD, 0, krh, DPAD, (long)T_*DPAD, 0,
              att, 0, 0, T_, (long)T_*T_, 0, 0, 0, attScale, 0, 1, BATCH*NH,
              T_, T_, DPAD);
        softmax_att_kernel<<<BATCH*NH*T_, 256>>>(att, lengths, atth, attl);
        convT_tran_kernel<<<dim3(T_/32, (HD+31)/32, BATCH*NH), dim3(32,8)>>>(qkv, vTth, vTtl);
        // o = att @ vTt^T  (split outputs only)
        tgemm(atth, attl, T_, (long)NH*T_*T_, (long)T_*T_,
              vTth, T_, (long)NH*HD*T_, (long)HD*T_,
              0, oh, ol, BATCH*DMODEL, DMODEL, HD,
              0, 0, 1.f, 0, NH, BATCH*NH, T_, HD, T_);
        // o2 = o @ Wo^T + bo (into qkv scratch)
        tgemm(oh, ol, DMODEL, 0,0, w1h, DMODEL, 0,0,
              qkv, 0, 0, DMODEL, 0,0, t_bo + (long)l*DMODEL, 0, 1.f, 0, 1, 1,
              MT, DMODEL, DMODEL);
        add_ln_kernel<<<MT, 256>>>(x, qkv, t_ln1g + (long)l*DMODEL,
                                   t_ln1b + (long)l*DMODEL, x, xh, xl);
        tgemm(xh, xl, DMODEL, 0,0, w2h, DMODEL, 0,0,
              0, ffh, ffl, DFF, 0,0, t_b1 + (long)l*DFF, 0, 1.f, 1, 1, 1,
              MT, DFF, DMODEL);
        tgemm(ffh, ffl, DFF, 0,0, w3h, DFF, 0,0,
              qkv, 0, 0, DMODEL, 0,0, t_b2 + (long)l*DMODEL, 0, 1.f, 0, 1, 1,
              MT, DMODEL, DFF);
        add_ln_kernel<<<MT, 256>>>(x, qkv, t_ln2g + (long)l*DMODEL,
                                   t_ln2b + (long)l*DMODEL, x, xh, xl);
    }

    // ---------------- head ----------------
    pool_kernel<<<dim3(BATCH, 4), 132>>>(x, lengths, pooled, plh, pll);
    wsplit(stat, sth, stl, BATCH*64);
    wsplit(static_W, w0h, w0l, 512*64);
    tgemm(sth, stl, 64, 0,0, w0h, 64, 0,0,
          0, plh + DMODEL, pll + DMODEL, DFINAL, 0,0,
          static_b, 0, 1.f, 0, 1, 1, BATCH, 512, 64);
    wsplit(mlp_W1, w1h, w1l, DFINAL*DFINAL);
    tgemm(plh, pll, DFINAL, 0,0, w1h, DFINAL, 0,0,
          hid, 0, 0, DFINAL, 0,0, mlp_b1, 0, 1.f, 1, 1, 1, BATCH, DFINAL, DFINAL);
    final_out_kernel<<<32, 256>>>(hid, mlp_W2, mlp_b2, out);
    (void)in_sizes; (void)n_in; (void)out_size;
}

// round 16
// speedup vs baseline: 1.4229x; 1.0086x over previous
#include <cuda_runtime.h>
#include <cuda_fp16.h>
#include <math.h>
#include <stdint.h>

typedef __half f16;

// ---------------- problem constants ----------------
constexpr int SE_    = 128;
constexpr int T_     = 256;
constexpr int BATCH  = 128;
constexpr int NH     = 4;
constexpr int DFF    = 128;
constexpr int DFEAT  = 1024;
constexpr int DMODEL = 528;
constexpr int DFINAL = 1040;
constexpr int HD     = 132;
constexpr int DPAD   = 136;               // HD padded to 16B-aligned rows
constexpr int LDQ    = BATCH*3*DMODEL;    // 202752

// ---------------- fp32 scratch ----------------
__device__ float g_hg  [(size_t)BATCH*SE_*DFEAT];
__device__ float g_v   [(size_t)BATCH*SE_*DFEAT];
__device__ float g_skip[(size_t)BATCH*SE_*DFEAT];
__device__ float g_S   [(size_t)BATCH*SE_*SE_];
__device__ float g_W   [(size_t)BATCH*SE_*SE_];
__device__ float g_x   [(size_t)T_*BATCH*DMODEL];
__device__ float g_qkv [(size_t)T_*BATCH*3*DMODEL];
__device__ float g_pool[(size_t)BATCH*DFINAL];
__device__ float g_hid [(size_t)BATCH*DFINAL];

// ---------------- fp16 hi/lo split scratch ----------------
__device__ f16 g_hg_h [(size_t)BATCH*SE_*DFEAT];
__device__ f16 g_hg_l [(size_t)BATCH*SE_*DFEAT];
__device__ f16 g_q_h  [(size_t)BATCH*SE_*DFEAT];
__device__ f16 g_q_l  [(size_t)BATCH*SE_*DFEAT];
__device__ f16 g_k_h  [(size_t)BATCH*SE_*DFEAT];
__device__ f16 g_k_l  [(size_t)BATCH*SE_*DFEAT];
__device__ f16 g_vT_h [(size_t)BATCH*DFEAT*SE_];
__device__ f16 g_vT_l [(size_t)BATCH*DFEAT*SE_];
__device__ f16 g_E_h  [(size_t)BATCH*SE_*SE_];
__device__ f16 g_E_l  [(size_t)BATCH*SE_*SE_];
__device__ f16 g_x_h  [(size_t)T_*BATCH*DMODEL];
__device__ f16 g_x_l  [(size_t)T_*BATCH*DMODEL];
__device__ f16 g_qr_h [(size_t)BATCH*NH*T_*DPAD];
__device__ f16 g_qr_l [(size_t)BATCH*NH*T_*DPAD];
__device__ f16 g_kr_h [(size_t)BATCH*NH*T_*DPAD];
__device__ f16 g_kr_l [(size_t)BATCH*NH*T_*DPAD];
__device__ f16 g_att_h[(size_t)BATCH*NH*T_*T_];
__device__ f16 g_att_l[(size_t)BATCH*NH*T_*T_];
__device__ f16 g_vTt_h[(size_t)BATCH*NH*HD*T_];
__device__ f16 g_vTt_l[(size_t)BATCH*NH*HD*T_];
__device__ f16 g_o_h  [(size_t)T_*BATCH*DMODEL];
__device__ f16 g_o_l  [(size_t)T_*BATCH*DMODEL];
__device__ f16 g_ff_h [(size_t)T_*BATCH*DFF];
__device__ f16 g_ff_l [(size_t)T_*BATCH*DFF];
__device__ f16 g_pl_h [(size_t)BATCH*DFINAL];
__device__ f16 g_pl_l [(size_t)BATCH*DFINAL];
__device__ f16 g_st_h [(size_t)BATCH*64];
__device__ f16 g_st_l [(size_t)BATCH*64];
constexpr size_t WBN = 1081600;   // >= mlp_W1 (1040*1040), >= Wqkv slice
__device__ f16 g_w0_h[WBN]; __device__ f16 g_w0_l[WBN];
__device__ f16 g_w1_h[WBN]; __device__ f16 g_w1_l[WBN];
__device__ f16 g_w2_h[WBN]; __device__ f16 g_w2_l[WBN];
__device__ f16 g_w3_h[WBN]; __device__ f16 g_w3_l[WBN];

// ---------------- helpers ----------------
__device__ __forceinline__ void split1(float v, f16& h, f16& l) {
    h = __float2half_rn(v);
    l = __float2half_rn(v - __half2float(h));
}
__device__ __forceinline__ uint32_t smem_u32(const void* p) {
    uint32_t a;
    asm("{ .reg .u64 t; cvta.to.shared.u64 t, %1; cvt.u32.u64 %0, t; }" : "=r"(a) : "l"(p));
    return a;
}
__device__ __forceinline__ void mma_f16(float* d, const uint32_t* a, const uint32_t* b) {
    asm("mma.sync.aligned.m16n8k16.row.col.f32.f16.f16.f32 "
        "{%0,%1,%2,%3}, {%4,%5,%6,%7}, {%8,%9}, {%0,%1,%2,%3};"
        : "+f"(d[0]), "+f"(d[1]), "+f"(d[2]), "+f"(d[3])
        : "r"(a[0]), "r"(a[1]), "r"(a[2]), "r"(a[3]), "r"(b[0]), "r"(b[1]));
}
#define LDSM4(r0,r1,r2,r3,addr) \
    asm volatile("ldmatrix.sync.aligned.m8n8.x4.shared.b16 {%0,%1,%2,%3}, [%4];" \
        : "=r"(r0), "=r"(r1), "=r"(r2), "=r"(r3) : "r"(addr))
#define CPASYNC(dst, src, zf) \
    asm volatile("cp.async.cg.shared.global [%0], [%1], 16, %2;" \
        :: "r"(dst), "l"(src), "r"(zf) : "memory")

// =====================================================================
// HMMA 2xFP16 NT GEMM on pre-split operands.
// acc += Ah*Bh + Al*Bh. Block tile 128x128, K-chunk 32, 3-stage cp.async,
// ldmatrix, pitch-80 smem. 2 CTAs/SM.
// =====================================================================
constexpr int TGP = 80;        // bytes per smem row
constexpr int TGT = 128*TGP;   // 10240 bytes per tile
constexpr int TGB = 3*TGT;     // Ah, Al, Bh = 30720
constexpr int TGS = 3*TGB;     // 92160 bytes (3 stages) -> 2 CTAs fit

__global__ __launch_bounds__(256, 2) void tgemm_kernel(
    const f16* __restrict__ Ah, const f16* __restrict__ Al, int lda, long sA1, long sA2,
    const f16* __restrict__ Bh, int ldb, long sB1, long sB2,
    float* __restrict__ C, f16* __restrict__ Ch, f16* __restrict__ Cl,
    int ldc, long sC1, long sC2,
    const float* __restrict__ bias, const float* __restrict__ addend,
    float scale, int doRelu, int zdiv, int M, int N, int K)
{
    extern __shared__ char smraw[];
    uint32_t sb = smem_u32(smraw);
    int tid = threadIdx.x, wid = tid >> 5, lane = tid & 31;
    int wm = wid & 3, wn = wid >> 2;
    int g = lane >> 2, t4 = lane & 3;

    int z = blockIdx.z, z1 = z / zdiv, z2 = z % zdiv;
    const f16* A_h = Ah + z1*sA1 + z2*sA2;
    const f16* A_l = Al + z1*sA1 + z2*sA2;
    const f16* B_h = Bh + z1*sB1 + z2*sB2;
    float* Cb = C ? C + z1*sC1 + z2*sC2 : (float*)0;
    f16* Chb = Ch ? Ch + z1*sC1 + z2*sC2 : (f16*)0;
    f16* Clb = Cl ? Cl + z1*sC1 + z2*sC2 : (f16*)0;
    const float* Db = addend ? addend + z1*sC1 + z2*sC2 : (const float*)0;

    int bm0 = blockIdx.y * 128;
    int bn0 = blockIdx.x * 128;
    int nk = (K + 31) >> 5;

    auto issue = [&](int c, int buf) {
        int k0 = c << 5;
        uint32_t bb = sb + (uint32_t)buf * TGB;
        #pragma unroll
        for (int j = 0; j < 6; j++) {
            int u = tid + j * 256;
            int tile = j >> 1;
            int within = u & 511;
            int rr = within >> 2, c4 = within & 3;
            int gk = k0 + c4 * 8;
            int zf = 2 * (K - gk); zf = zf < 0 ? 0 : (zf > 16 ? 16 : zf);
            uint32_t sa = bb + (uint32_t)tile*TGT + rr * TGP + c4 * 16;
            if (tile == 0) {
                int m = bm0 + rr;
                int z8 = (m < M) ? zf : 0;
                const f16* p = z8 ? (A_h + (long)m * lda + gk) : A_h;
                CPASYNC(sa, p, z8);
            } else if (tile == 1) {
                int m = bm0 + rr;
                int z8 = (m < M) ? zf : 0;
                const f16* p = z8 ? (A_l + (long)m * lda + gk) : A_l;
                CPASYNC(sa, p, z8);
            } else {
                int n = bn0 + rr;
                int z8 = (n < N) ? zf : 0;
                const f16* p = z8 ? (B_h + (long)n * ldb + gk) : B_h;
                CPASYNC(sa, p, z8);
            }
        }
        asm volatile("cp.async.commit_group;" ::: "memory");
    };

    issue(0, 0);
    if (nk > 1) issue(1, 1);

    float acc[2][8][4];
    #pragma unroll
    for (int i = 0; i < 2; i++)
        #pragma unroll
        for (int j = 0; j < 8; j++)
            #pragma unroll
            for (int d = 0; d < 4; d++) acc[i][j][d] = 0.f;

    int aRow  = wm*32 + (lane & 7) + ((lane >> 3) & 1) * 8;
    int aColB = (lane >> 4) * 16;
    int bRow  = wn*64 + (lane & 7) + (lane >> 4) * 8;
    int bColB = ((lane >> 3) & 1) * 16;

    for (int c = 0; c < nk; c++) {
        if (c + 1 < nk) asm volatile("cp.async.wait_group 1;" ::: "memory");
        else            asm volatile("cp.async.wait_group 0;" ::: "memory");
        __syncthreads();
        if (c + 2 < nk) issue(c + 2, (c + 2) % 3);

        uint32_t bb = sb + (uint32_t)(c % 3) * TGB;
        uint32_t aH = bb + aRow * TGP + aColB;
        uint32_t aL = aH + TGT;
        uint32_t bH = bb + 2*TGT + bRow * TGP + bColB;

        int smax = (K - (c << 5) + 15) >> 4;
        if (smax > 2) smax = 2;
        #pragma unroll 2
        for (int s = 0; s < smax; s++) {
            uint32_t ah[2][4], al[2][4], bh[8][2];
            #pragma unroll
            for (int mt = 0; mt < 2; mt++) {
                LDSM4(ah[mt][0], ah[mt][1], ah[mt][2], ah[mt][3], aH + mt*(16*TGP) + s*32);
                LDSM4(al[mt][0], al[mt][1], al[mt][2], al[mt][3], aL + mt*(16*TGP) + s*32);
            }
            #pragma unroll
            for (int p = 0; p < 4; p++) {
                LDSM4(bh[2*p][0], bh[2*p][1], bh[2*p+1][0], bh[2*p+1][1], bH + p*(16*TGP) + s*32);
            }
            #pragma unroll
            for (int mt = 0; mt < 2; mt++)
                #pragma unroll
                for (int nt = 0; nt < 8; nt++)
                    mma_f16(acc[mt][nt], ah[mt], bh[nt]);
            #pragma unroll
            for (int mt = 0; mt < 2; mt++)
                #pragma unroll
                for (int nt = 0; nt < 8; nt++)
                    mma_f16(acc[mt][nt], al[mt], bh[nt]);
        }
    }

    // epilogue
    #pragma unroll
    for (int mt = 0; mt < 2; mt++) {
        int rlo = bm0 + wm*32 + mt*16 + g;
        int rhi = rlo + 8;
        #pragma unroll
        for (int nt = 0; nt < 8; nt++) {
            int c0 = bn0 + wn*64 + nt*8 + t4*2;
            #pragma unroll
            for (int hh = 0; hh < 2; hh++) {
                int row = hh ? rhi : rlo;
                if (row >= M) continue;
                #pragma unroll
                for (int cc = 0; cc < 2; cc++) {
                    int n = c0 + cc;
                    if (n >= N) continue;
                    long ci = (long)row * ldc + n;
                    float vv = acc[mt][nt][hh*2 + cc] * scale;
                    if (bias) vv += __ldg(bias + n);
                    if (Db)   vv += Db[ci];
                    if (doRelu) vv = fmaxf(vv, 0.f);
                    if (Cb) Cb[ci] = vv;
                    if (Chb) { f16 h, l; split1(vv, h, l); Chb[ci] = h; Clb[ci] = l; }
                }
            }
        }
    }
}

// =====================================================================
// Fused attention: scores(128x256 tile, K=DPAD) + masked softmax + split.
// Same mainloop math as tgemm (bit-identical logits); epilogue does the
// row softmax (t4-shfl + wn-pair smem reduce) and writes split f16 probs.
// =====================================================================
constexpr int ATT_A   = 128*TGP;             // 10240
constexpr int ATT_B   = 256*TGP;             // 20480
constexpr int ATT_BUF = 2*ATT_A + ATT_B;     // 40960
constexpr int ATT_S   = 3*ATT_BUF;           // 122880

__global__ __launch_bounds__(256, 1) void att_fused_kernel(
    const f16* __restrict__ qrh, const f16* __restrict__ qrl,
    const f16* __restrict__ krh, const int* __restrict__ lengths,
    f16* __restrict__ atth, f16* __restrict__ attl, float scale)
{
    extern __shared__ char smraw[];
    uint32_t sb = smem_u32(smraw);
    __shared__ float red[2][128];
    int tid = threadIdx.x, wid = tid >> 5, lane = tid & 31;
    int wm = wid & 3, wn = wid >> 2;
    int g = lane >> 2, t4 = lane & 3;

    int bh = blockIdx.z;
    int len = __ldg(lengths + (bh >> 2));
    int bm0 = blockIdx.y * 128;
    const f16* A_h = qrh + (long)bh*T_*DPAD;
    const f16* A_l = qrl + (long)bh*T_*DPAD;
    const f16* B_h = krh + (long)bh*T_*DPAD;
    const int K = DPAD;
    int nk = (K + 31) >> 5;   // 5

    auto issue = [&](int c, int buf) {
        int k0 = c << 5;
        uint32_t bb = sb + (uint32_t)buf * ATT_BUF;
        #pragma unroll
        for (int j = 0; j < 8; j++) {
            int gk, zf;
            uint32_t sa;
            const f16* p;
            if (j < 4) {
                int u = tid + (j & 1) * 256;     // 0..511
                int rr = u >> 2, c4 = u & 3;
                gk = k0 + c4 * 8;
                zf = 2 * (K - gk); zf = zf < 0 ? 0 : (zf > 16 ? 16 : zf);
                if (j < 2) { sa = bb + rr*TGP + c4*16;          p = zf ? (A_h + (long)(bm0+rr)*DPAD + gk) : A_h; }
                else       { sa = bb + ATT_A + rr*TGP + c4*16;  p = zf ? (A_l + (long)(bm0+rr)*DPAD + gk) : A_l; }
            } else {
                int u = tid + (j - 4) * 256;     // 0..1023
                int rr = u >> 2, c4 = u & 3;
                gk = k0 + c4 * 8;
                zf = 2 * (K - gk); zf = zf < 0 ? 0 : (zf > 16 ? 16 : zf);
                sa = bb + 2*ATT_A + rr*TGP + c4*16;
                p = zf ? (B_h + (long)rr*DPAD + gk) : B_h;
            }
            CPASYNC(sa, p, zf);
        }
        asm volatile("cp.async.commit_group;" ::: "memory");
    };

    issue(0, 0);
    issue(1, 1);

    float acc[2][2][8][4];   // [nh][mt][nt][dd]
    #pragma unroll
    for (int a2 = 0; a2 < 2; a2++)
        #pragma unroll
        for (int i = 0; i < 2; i++)
            #pragma unroll
            for (int j = 0; j < 8; j++)
                #pragma unroll
                for (int d = 0; d < 4; d++) acc[a2][i][j][d] = 0.f;

    int aRow  = wm*32 + (lane & 7) + ((lane >> 3) & 1) * 8;
    int aColB = (lane >> 4) * 16;
    int bRowB = wn*64 + (lane & 7) + (lane >> 4) * 8;
    int bColB = ((lane >> 3) & 1) * 16;

    for (int c = 0; c < nk; c++) {
        if (c + 1 < nk) asm volatile("cp.async.wait_group 1;" ::: "memory");
        else            asm volatile("cp.async.wait_group 0;" ::: "memory");
        __syncthreads();
        if (c + 2 < nk) issue(c + 2, (c + 2) % 3);

        uint32_t bb = sb + (uint32_t)(c % 3) * ATT_BUF;
        uint32_t aH = bb + aRow * TGP + aColB;
        uint32_t aL = aH + ATT_A;
        uint32_t bB = bb + 2*ATT_A;

        int smax = (K - (c << 5) + 15) >> 4;
        if (smax > 2) smax = 2;
        #pragma unroll 2
        for (int s = 0; s < smax; s++) {
            uint32_t ah[2][4], al[2][4], bh[2][8][2];
            #pragma unroll
            for (int mt = 0; mt < 2; mt++) {
                LDSM4(ah[mt][0], ah[mt][1], ah[mt][2], ah[mt][3], aH + mt*(16*TGP) + s*32);
                LDSM4(al[mt][0], al[mt][1], al[mt][2], al[mt][3], aL + mt*(16*TGP) + s*32);
            }
            #pragma unroll
            for (int nh = 0; nh < 2; nh++) {
                uint32_t bBase = bB + (nh*128 + bRowB) * TGP + bColB;
                #pragma unroll
                for (int p = 0; p < 4; p++)
                    LDSM4(bh[nh][2*p][0], bh[nh][2*p][1], bh[nh][2*p+1][0], bh[nh][2*p+1][1],
                          bBase + p*(16*TGP) + s*32);
            }
            #pragma unroll
            for (int nh = 0; nh < 2; nh++)
                #pragma unroll
                for (int mt = 0; mt < 2; mt++)
                    #pragma unroll
                    for (int nt = 0; nt < 8; nt++)
                        mma_f16(acc[nh][mt][nt], ah[mt], bh[nh][nt]);
            #pragma unroll
            for (int nh = 0; nh < 2; nh++)
                #pragma unroll
                for (int mt = 0; mt < 2; mt++)
                    #pragma unroll
                    for (int nt = 0; nt < 8; nt++)
                        mma_f16(acc[nh][mt][nt], al[mt], bh[nh][nt]);
        }
    }

    // -------- fused masked softmax epilogue --------
    // row_local(mt,hh) = wm*32 + mt*16 + hh*8 + g; col = nh*128 + wn*64 + nt*8 + t4*2 + cc
    float rmax[2][2];
    #pragma unroll
    for (int mt = 0; mt < 2; mt++)
        #pragma unroll
        for (int hh = 0; hh < 2; hh++) rmax[mt][hh] = -3.0e38f;

    #pragma unroll
    for (int nh = 0; nh < 2; nh++)
        #pragma unroll
        for (int mt = 0; mt < 2; mt++)
            #pragma unroll
            for (int nt = 0; nt < 8; nt++)
                #pragma unroll
                for (int hh = 0; hh < 2; hh++)
                    #pragma unroll
                    for (int cc = 0; cc < 2; cc++) {
                        int col = nh*128 + wn*64 + nt*8 + t4*2 + cc;
                        float v = acc[nh][mt][nt][hh*2+cc] * scale;
                        if (col >= len) v = -1e9f;
                        acc[nh][mt][nt][hh*2+cc] = v;
                        rmax[mt][hh] = fmaxf(rmax[mt][hh], v);
                    }
    #pragma unroll
    for (int mt = 0; mt < 2; mt++)
        #pragma unroll
        for (int hh = 0; hh < 2; hh++) {
            float m = rmax[mt][hh];
            m = fmaxf(m, __shfl_xor_sync(0xffffffffu, m, 1));
            m = fmaxf(m, __shfl_xor_sync(0xffffffffu, m, 2));
            rmax[mt][hh] = m;
        }
    if (t4 == 0) {
        #pragma unroll
        for (int mt = 0; mt < 2; mt++)
            #pragma unroll
            for (int hh = 0; hh < 2; hh++)
                red[wn][wm*32 + mt*16 + hh*8 + g] = rmax[mt][hh];
    }
    __syncthreads();
    float gmax[2][2];
    #pragma unroll
    for (int mt = 0; mt < 2; mt++)
        #pragma unroll
        for (int hh = 0; hh < 2; hh++) {
            int r = wm*32 + mt*16 + hh*8 + g;
            gmax[mt][hh] = fmaxf(red[0][r], red[1][r]);
        }
    __syncthreads();

    float rsum[2][2];
    #pragma unroll
    for (int mt = 0; mt < 2; mt++)
        #pragma unroll
        for (int hh = 0; hh < 2; hh++) rsum[mt][hh] = 0.f;
    #pragma unroll
    for (int nh = 0; nh < 2; nh++)
        #pragma unroll
        for (int mt = 0; mt < 2; mt++)
            #pragma unroll
            for (int nt = 0; nt < 8; nt++)
                #pragma unroll
                for (int hh = 0; hh < 2; hh++)
                    #pragma unroll
                    for (int cc = 0; cc < 2; cc++) {
                        float e = expf(acc[nh][mt][nt][hh*2+cc] - gmax[mt][hh]);
                        acc[nh][mt][nt][hh*2+cc] = e;
                        rsum[mt][hh] += e;
                    }
    #pragma unroll
    for (int mt = 0; mt < 2; mt++)
        #pragma unroll
        for (int hh = 0; hh < 2; hh++) {
            float s = rsum[mt][hh];
            s += __shfl_xor_sync(0xffffffffu, s, 1);
            s += __shfl_xor_sync(0xffffffffu, s, 2);
            rsum[mt][hh] = s;
        }
    if (t4 == 0) {
        #pragma unroll
        for (int mt = 0; mt < 2; mt++)
            #pragma unroll
            for (int hh = 0; hh < 2; hh++)
                red[wn][wm*32 + mt*16 + hh*8 + g] = rsum[mt][hh];
    }
    __syncthreads();
    float ginv[2][2];
    #pragma unroll
    for (int mt = 0; mt < 2; mt++)
        #pragma unroll
        for (int hh = 0; hh < 2; hh++) {
            int r = wm*32 + mt*16 + hh*8 + g;
            ginv[mt][hh] = 1.0f / (red[0][r] + red[1][r]);
        }

    f16* ah_out = atth + (long)bh*T_*T_;
    f16* al_out = attl + (long)bh*T_*T_;
    #pragma unroll
    for (int nh = 0; nh < 2; nh++)
        #pragma unroll
        for (int mt = 0; mt < 2; mt++)
            #pragma unroll
            for (int hh = 0; hh < 2; hh++) {
                int row = bm0 + wm*32 + mt*16 + hh*8 + g;
                #pragma unroll
                for (int nt = 0; nt < 8; nt++)
                    #pragma unroll
                    for (int cc = 0; cc < 2; cc++) {
                        int col = nh*128 + wn*64 + nt*8 + t4*2 + cc;
                        float p = acc[nh][mt][nt][hh*2+cc] * ginv[mt][hh];
                        f16 h, l; split1(p, h, l);
                        ah_out[(long)row*T_ + col] = h;
                        al_out[(long)row*T_ + col] = l;
                    }
            }
}

// ---------------- converts / repacks ----------------
__global__ void split_kernel(const float* __restrict__ in,
                             f16* __restrict__ h, f16* __restrict__ l, int n)
{
    int i = blockIdx.x * 256 + threadIdx.x;
    if (i < n) { f16 hv, lv; split1(in[i], hv, lv); h[i] = hv; l[i] = lv; }
}

// prop v [b][se][feat] -> vT [b][feat][se], split
__global__ void convT_prop_kernel(const float* __restrict__ v,
                                  f16* __restrict__ th, f16* __restrict__ tl)
{
    __shared__ float tile[32][33];
    int b = blockIdx.z;
    int f0 = blockIdx.x * 32, s0 = blockIdx.y * 32;
    int tx = threadIdx.x, ty = threadIdx.y;   // 32 x 8
    const float* vb = v + (long)b*SE_*DFEAT;
    #pragma unroll
    for (int k2 = 0; k2 < 4; k2++)
        tile[ty + k2*8][tx] = vb[(long)(s0 + ty + k2*8)*DFEAT + f0 + tx];
    __syncthreads();
    f16* thb = th + (long)b*DFEAT*SE_;
    f16* tlb = tl + (long)b*DFEAT*SE_;
    #pragma unroll
    for (int k2 = 0; k2 < 4; k2++) {
        float val = tile[tx][ty + k2*8];
        long oi = (long)(f0 + ty + k2*8)*SE_ + s0 + tx;
        f16 h, l; split1(val, h, l); thb[oi] = h; tlb[oi] = l;
    }
}

// tran v slice of qkv -> vTt [bh][d][t], split
__global__ void convT_tran_kernel(const float* __restrict__ qkv,
                                  f16* __restrict__ th, f16* __restrict__ tl)
{
    __shared__ float tile[32][33];
    int bh = blockIdx.z; int b = bh >> 2, h = bh & 3;
    int t0 = blockIdx.x * 32, d0 = blockIdx.y * 32;
    int tx = threadIdx.x, ty = threadIdx.y;   // 32 x 8
    const float* base = qkv + (long)b*3*DMODEL + 2*DMODEL + h*HD;
    #pragma unroll
    for (int k2 = 0; k2 < 4; k2++) {
        int d = d0 + tx;
        tile[ty + k2*8][tx] = (d < HD) ? base[(long)(t0 + ty + k2*8)*LDQ + d] : 0.f;
    }
    __syncthreads();
    f16* thb = th + (long)bh*HD*T_;
    f16* tlb = tl + (long)bh*HD*T_;
    #pragma unroll
    for (int k2 = 0; k2 < 4; k2++) {
        int d = d0 + ty + k2*8;
        if (d < HD) {
            float val = tile[tx][ty + k2*8];
            long oi = (long)d*T_ + t0 + tx;
            f16 hh, ll; split1(val, hh, ll); thb[oi] = hh; tlb[oi] = ll;
        }
    }
}

// q,k parts of qkv -> [bh][t][DPAD] split (zero-pad 132->136)
__global__ void repack_qk_kernel(const float* __restrict__ qkv,
                                 f16* __restrict__ qh, f16* __restrict__ ql,
                                 f16* __restrict__ kh, f16* __restrict__ kl)
{
    long idx = (long)blockIdx.x * 256 + threadIdx.x;
    if (idx >= (long)BATCH*NH*T_*DPAD) return;
    int d = (int)(idx % DPAD);
    long r = idx / DPAD;
    int t = (int)(r % T_);
    int bh = (int)(r / T_);
    int b = bh >> 2, h = bh & 3;
    long src = (long)t*LDQ + (long)b*3*DMODEL + h*HD;
    float qv = (d < HD) ? qkv[src + d] : 0.f;
    float kv = (d < HD) ? qkv[src + DMODEL + d] : 0.f;
    f16 hh, ll;
    split1(qv, hh, ll); qh[idx] = hh; ql[idx] = ll;
    split1(kv, hh, ll); kh[idx] = hh; kl[idx] = ll;
}

// ---------------- elementwise / reduction kernels ---------------------------
__global__ void build_hg_kernel(const float* __restrict__ src,
                                const float* __restrict__ R_u,
                                float* __restrict__ hg,
                                f16* __restrict__ hh, f16* __restrict__ hl)
{
    int idx = blockIdx.x * blockDim.x + threadIdx.x;
    if (idx >= T_*BATCH*SE_) return;
    int se = idx % SE_;
    int tb = idx / SE_;
    int b = tb % BATCH;
    int t = tb / BATCH;
    float s = src[(long)t*BATCH*2*SE_ + (long)b*2*SE_ + se];
    long base = (long)b*SE_*DFEAT + (long)se*DFEAT + t*4;
    #pragma unroll
    for (int d = 0; d < 4; d++) {
        float v = fmaxf(s * R_u[se*4 + d], 0.f);
        hg[base + d] = v;
        f16 h, l; split1(v, h, l); hh[base + d] = h; hl[base + d] = l;
    }
}

__global__ __launch_bounds__(128) void softmax_prop_kernel(
    float* __restrict__ S, float* __restrict__ W,
    f16* __restrict__ Eh, f16* __restrict__ El, int useW)
{
    int row = blockIdx.x;
    float* sr = S + (long)row*SE_;
    float* wr = W + (long)row*SE_;
    int tid = threadIdx.x;
    float v = sr[tid];
    __shared__ float red[4];
    float m = v;
    #pragma unroll
    for (int o = 16; o > 0; o >>= 1) m = fmaxf(m, __shfl_xor_sync(0xffffffffu, m, o));
    if ((tid & 31) == 0) red[tid >> 5] = m;
    __syncthreads();
    m = fmaxf(fmaxf(red[0], red[1]), fmaxf(red[2], red[3]));
    float e = expf(v - m);
    float s = e;
    #pragma unroll
    for (int o = 16; o > 0; o >>= 1) s += __shfl_xor_sync(0xffffffffu, s, o);
    __syncthreads();
    if ((tid & 31) == 0) red[tid >> 5] = s;
    __syncthreads();
    s = red[0] + red[1] + red[2] + red[3];
    float alpha = e / s;
    float wprev = useW ? wr[tid] : 1.0f;
    float E = alpha * wprev;
    f16 h, l; split1(E, h, l);
    Eh[(long)row*SE_ + tid] = h;
    El[(long)row*SE_ + tid] = l;
    wr[tid] = alpha;
}

__global__ void build_x_kernel(const float* __restrict__ hg,
                               const float* __restrict__ times,
                               float* __restrict__ x,
                               f16* __restrict__ xh, f16* __restrict__ xl)
{
    long idx = (long)blockIdx.x * blockDim.x + threadIdx.x;
    if (idx >= (long)T_*BATCH*DMODEL) return;
    int c = (int)(idx % DMODEL);
    long tb = idx / DMODEL;
    int b = (int)(tb % BATCH);
    int t = (int)(tb / BATCH);
    float v;
    if (c < 512) {
        int se = c >> 2, d = c & 3;
        v = hg[(long)b*SE_*DFEAT + (long)se*DFEAT + t*4 + d];
    } else {
        int i = c - 512;
        int ii = (i < 8) ? i : i - 8;
        float tsv = powf(256.0f, (float)ii * (1.0f/7.0f));
        float st = times[(long)t*BATCH + b] / tsv;
        v = (i < 8) ? sinf(st) : cosf(st);
    }
    x[idx] = v;
    f16 h, l; split1(v, h, l); xh[idx] = h; xl[idx] = l;
}

// Vectorized: 256 threads, thread t handles cols {2t, 2t+1}; t<8 also {512+2t, 513+2t}.
__global__ __launch_bounds__(256) void add_ln_kernel(
    const float* __restrict__ xin, const float* __restrict__ res,
    const float* __restrict__ g, const float* __restrict__ be,
    float* __restrict__ out, f16* __restrict__ oh, f16* __restrict__ ol)
{
    int row = blockIdx.x;
    const float2* xr = (const float2*)(xin + (long)row*DMODEL);
    const float2* rr = (const float2*)(res + (long)row*DMODEL);
    float2* orow = (float2*)(out + (long)row*DMODEL);
    __half2* ohrow = (__half2*)(oh + (long)row*DMODEL);
    __half2* olrow = (__half2*)(ol + (long)row*DMODEL);
    int tid = threadIdx.x;
    int lane = tid & 31, wrp = tid >> 5;
    __shared__ float red[8];

    float2 a = xr[tid], b = rr[tid];
    float2 v0 = make_float2(a.x + b.x, a.y + b.y);
    float2 v1 = make_float2(0.f, 0.f);
    bool extra = tid < 8;
    if (extra) {
        float2 a2 = xr[256 + tid], b2 = rr[256 + tid];
        v1 = make_float2(a2.x + b2.x, a2.y + b2.y);
    }
    float s = v0.x + v0.y + v1.x + v1.y;
    #pragma unroll
    for (int o = 16; o > 0; o >>= 1) s += __shfl_xor_sync(0xffffffffu, s, o);
    if (lane == 0) red[wrp] = s;
    __syncthreads();
    s = 0.f;
    #pragma unroll
    for (int i = 0; i < 8; i++) s += red[i];
    float mean = s * (1.0f/DMODEL);
    __syncthreads();

    float d0x = v0.x - mean, d0y = v0.y - mean;
    float vs = d0x*d0x + d0y*d0y;
    if (extra) { float d1x = v1.x - mean, d1y = v1.y - mean; vs += d1x*d1x + d1y*d1y; }
    #pragma unroll
    for (int o = 16; o > 0; o >>= 1) vs += __shfl_xor_sync(0xffffffffu, vs, o);
    if (lane == 0) red[wrp] = vs;
    __syncthreads();
    vs = 0.f;
    #pragma unroll
    for (int i = 0; i < 8; i++) vs += red[i];
    float rstd = rsqrtf(vs * (1.0f/DMODEL) + 1e-5f);

    {
        int c = 2*tid;
        float o0 = (v0.x - mean) * rstd * __ldg(g + c)     + __ldg(be + c);
        float o1 = (v0.y - mean) * rstd * __ldg(g + c + 1) + __ldg(be + c + 1);
        orow[tid] = make_float2(o0, o1);
        f16 h0, l0, h1, l1;
        split1(o0, h0, l0); split1(o1, h1, l1);
        ohrow[tid] = __halves2half2(h0, h1);
        olrow[tid] = __halves2half2(l0, l1);
    }
    if (extra) {
        int c = 512 + 2*tid;
        float o0 = (v1.x - mean) * rstd * __ldg(g + c)     + __ldg(be + c);
        float o1 = (v1.y - mean) * rstd * __ldg(g + c + 1) + __ldg(be + c + 1);
        orow[256 + tid] = make_float2(o0, o1);
        f16 h0, l0, h1, l1;
        split1(o0, h0, l0); split1(o1, h1, l1);
        ohrow[256 + tid] = __halves2half2(h0, h1);
        olrow[256 + tid] = __halves2half2(l0, l1);
    }
}

__global__ void pool_kernel(const float* __restrict__ x,
                            const int* __restrict__ lengths,
                            float* __restrict__ pooled,
                            f16* __restrict__ ph, f16* __restrict__ pl)
{
    int b = blockIdx.x;
    int c = blockIdx.y * 132 + threadIdx.x;
    if (threadIdx.x >= 132 || c >= DMODEL) return;
    int len = lengths[b];
    float s = 0.f;
    for (int t = 0; t < len; t++)
        s += x[(long)t*BATCH*DMODEL + (long)b*DMODEL + c];
    float v = s / ((float)len + 1.0f);
    long oi = (long)b*DFINAL + c;
    pooled[oi] = v;
    f16 h, l; split1(v, h, l); ph[oi] = h; pl[oi] = l;
}

__global__ __launch_bounds__(256) void final_out_kernel(
    const float* __restrict__ hid, const float* __restrict__ W2,
    const float* __restrict__ b2, float* __restrict__ out)
{
    int p = blockIdx.x * 8 + (threadIdx.x >> 5);
    if (p >= BATCH*2) return;
    int b = p >> 1, c = p & 1;
    int lane = threadIdx.x & 31;
    float s = 0.f;
    for (int k = lane; k < DFINAL; k += 32)
        s += hid[(long)b*DFINAL + k] * W2[(long)c*DFINAL + k];
    #pragma unroll
    for (int o = 16; o > 0; o >>= 1) s += __shfl_xor_sync(0xffffffffu, s, o);
    if (lane == 0) out[p] = s + b2[c];
}

// ---------------- host helpers ----------------
static void tgemm(const f16* Ah, const f16* Al, int lda, long sA1, long sA2,
                  const f16* Bh, int ldb, long sB1, long sB2,
                  float* C, f16* Ch, f16* Cl, int ldc, long sC1, long sC2,
                  const float* bias, const float* add, float scale, int relu,
                  int zdiv, int nz, int M, int N, int K)
{
    dim3 grid((N+127)/128, (M+127)/128, nz);
    tgemm_kernel<<<grid, 256, TGS>>>(Ah, Al, lda, sA1, sA2, Bh, ldb, sB1, sB2,
                                     C, Ch, Cl, ldc, sC1, sC2, bias, add, scale,
                                     relu, zdiv, M, N, K);
}
static void wsplit(const float* in, f16* h, f16* l, int n) {
    split_kernel<<<(n+255)/256, 256>>>(in, h, l, n);
}

extern "C" void kernel_launch(void* const* d_in, const int* in_sizes, int n_in,
                              void* d_out, int out_size)
{
    const float* src      = (const float*)d_in[0];
    const float* times    = (const float*)d_in[1];
    const int*   lengths  = (const int*)  d_in[2];
    const float* stat     = (const float*)d_in[3];
    const float* R_u      = (const float*)d_in[4];
    const float* static_W = (const float*)d_in[5];
    const float* static_b = (const float*)d_in[6];
    const float* p_Wq     = (const float*)d_in[7];
    const float* p_Wk     = (const float*)d_in[8];
    const float* p_Wv     = (const float*)d_in[9];
    const float* p_bq     = (const float*)d_in[10];
    const float* p_bk     = (const float*)d_in[11];
    const float* p_bv     = (const float*)d_in[12];
    const float* p_Wskip  = (const float*)d_in[13];
    const float* p_bskip  = (const float*)d_in[14];
    const float* t_Wqkv   = (const float*)d_in[15];
    const float* t_bqkv   = (const float*)d_in[16];
    const float* t_Wo     = (const float*)d_in[17];
    const float* t_bo     = (const float*)d_in[18];
    const float* t_W1     = (const float*)d_in[19];
    const float* t_b1     = (const float*)d_in[20];
    const float* t_W2     = (const float*)d_in[21];
    const float* t_b2     = (const float*)d_in[22];
    const float* t_ln1g   = (const float*)d_in[23];
    const float* t_ln1b   = (const float*)d_in[24];
    const float* t_ln2g   = (const float*)d_in[25];
    const float* t_ln2b   = (const float*)d_in[26];
    const float* mlp_W1   = (const float*)d_in[27];
    const float* mlp_b1   = (const float*)d_in[28];
    const float* mlp_W2   = (const float*)d_in[29];
    const float* mlp_b2   = (const float*)d_in[30];
    float* out = (float*)d_out;

    cudaFuncSetAttribute(tgemm_kernel, cudaFuncAttributeMaxDynamicSharedMemorySize, TGS);
    cudaFuncSetAttribute(att_fused_kernel, cudaFuncAttributeMaxDynamicSharedMemorySize, ATT_S);

    float *hg,*v,*skip,*S,*W,*x,*qkv,*pooled,*hid;
    cudaGetSymbolAddress((void**)&hg,g_hg);
    cudaGetSymbolAddress((void**)&v,g_v);
    cudaGetSymbolAddress((void**)&skip,g_skip); cudaGetSymbolAddress((void**)&S,g_S);
    cudaGetSymbolAddress((void**)&W,g_W);   cudaGetSymbolAddress((void**)&x,g_x);
    cudaGetSymbolAddress((void**)&qkv,g_qkv);
    cudaGetSymbolAddress((void**)&pooled,g_pool); cudaGetSymbolAddress((void**)&hid,g_hid);

    f16 *hgh,*hgl,*qh,*ql,*kh,*kl,*vTh,*vTl,*Eh,*El,*xh,*xl;
    f16 *qrh,*qrl,*krh,*krl,*atth,*attl,*vTth,*vTtl,*oh,*ol,*ffh,*ffl,*plh,*pll,*sth,*stl;
    f16 *w0h,*w0l,*w1h,*w1l,*w2h,*w2l,*w3h,*w3l;
    cudaGetSymbolAddress((void**)&hgh,g_hg_h); cudaGetSymbolAddress((void**)&hgl,g_hg_l);
    cudaGetSymbolAddress((void**)&qh,g_q_h);   cudaGetSymbolAddress((void**)&ql,g_q_l);
    cudaGetSymbolAddress((void**)&kh,g_k_h);   cudaGetSymbolAddress((void**)&kl,g_k_l);
    cudaGetSymbolAddress((void**)&vTh,g_vT_h); cudaGetSymbolAddress((void**)&vTl,g_vT_l);
    cudaGetSymbolAddress((void**)&Eh,g_E_h);   cudaGetSymbolAddress((void**)&El,g_E_l);
    cudaGetSymbolAddress((void**)&xh,g_x_h);   cudaGetSymbolAddress((void**)&xl,g_x_l);
    cudaGetSymbolAddress((void**)&qrh,g_qr_h); cudaGetSymbolAddress((void**)&qrl,g_qr_l);
    cudaGetSymbolAddress((void**)&krh,g_kr_h); cudaGetSymbolAddress((void**)&krl,g_kr_l);
    cudaGetSymbolAddress((void**)&atth,g_att_h); cudaGetSymbolAddress((void**)&attl,g_att_l);
    cudaGetSymbolAddress((void**)&vTth,g_vTt_h); cudaGetSymbolAddress((void**)&vTtl,g_vTt_l);
    cudaGetSymbolAddress((void**)&oh,g_o_h);   cudaGetSymbolAddress((void**)&ol,g_o_l);
    cudaGetSymbolAddress((void**)&ffh,g_ff_h); cudaGetSymbolAddress((void**)&ffl,g_ff_l);
    cudaGetSymbolAddress((void**)&plh,g_pl_h); cudaGetSymbolAddress((void**)&pll,g_pl_l);
    cudaGetSymbolAddress((void**)&sth,g_st_h); cudaGetSymbolAddress((void**)&stl,g_st_l);
    cudaGetSymbolAddress((void**)&w0h,g_w0_h); cudaGetSymbolAddress((void**)&w0l,g_w0_l);
    cudaGetSymbolAddress((void**)&w1h,g_w1_h); cudaGetSymbolAddress((void**)&w1l,g_w1_l);
    cudaGetSymbolAddress((void**)&w2h,g_w2_h); cudaGetSymbolAddress((void**)&w2l,g_w2_l);
    cudaGetSymbolAddress((void**)&w3h,g_w3_h); cudaGetSymbolAddress((void**)&w3l,g_w3_l);

    const int M1 = BATCH*SE_;   // 16384
    const int MT = T_*BATCH;    // 32768

    build_hg_kernel<<<(T_*BATCH*SE_ + 255)/256, 256>>>(src, R_u, hg, hgh, hgl);

    // ---------------- prop layers ----------------
    for (int l = 0; l < 2; l++) {
        long wOff = (long)l*DFEAT*DFEAT;
        long bOff = (long)l*DFEAT;
        wsplit(p_Wq + wOff,    w0h, w0l, DFEAT*DFEAT);
        wsplit(p_Wk + wOff,    w1h, w1l, DFEAT*DFEAT);
        wsplit(p_Wv + wOff,    w2h, w2l, DFEAT*DFEAT);
        wsplit(p_Wskip + wOff, w3h, w3l, DFEAT*DFEAT);
        tgemm(hgh, hgl, DFEAT, 0,0, w0h, DFEAT, 0,0,
              0, qh, ql, DFEAT, 0,0, p_bq + bOff, 0, 1.f, 0, 1, 1, M1, DFEAT, DFEAT);
        tgemm(hgh, hgl, DFEAT, 0,0, w1h, DFEAT, 0,0,
              0, kh, kl, DFEAT, 0,0, p_bk + bOff, 0, 1.f, 0, 1, 1, M1, DFEAT, DFEAT);
        tgemm(hgh, hgl, DFEAT, 0,0, w2h, DFEAT, 0,0,
              v, 0, 0, DFEAT, 0,0, p_bv + bOff, 0, 1.f, 0, 1, 1, M1, DFEAT, DFEAT);
        tgemm(hgh, hgl, DFEAT, 0,0, w3h, DFEAT, 0,0,
              skip, 0, 0, DFEAT, 0,0, p_bskip + bOff, 0, 1.f, 0, 1, 1, M1, DFEAT, DFEAT);
        // scores[b] = q[b] @ k[b]^T / 32
        tgemm(qh, ql, DFEAT, (long)SE_*DFEAT, 0, kh, DFEAT, (long)SE_*DFEAT, 0,
              S, 0, 0, SE_, (long)SE_*SE_, 0, 0, 0, 0.03125f, 0, 1, BATCH,
              SE_, SE_, DFEAT);
        softmax_prop_kernel<<<BATCH*SE_, 128>>>(S, W, Eh, El, l > 0);
        convT_prop_kernel<<<dim3(DFEAT/32, SE_/32, BATCH), dim3(32,8)>>>(v, vTh, vTl);
        // hg = E @ vT^T + skip
        tgemm(Eh, El, SE_, (long)SE_*SE_, 0, vTh, SE_, (long)DFEAT*SE_, 0,
              hg, hgh, hgl, DFEAT, (long)SE_*DFEAT, 0, 0, skip, 1.f, 0, 1, BATCH,
              SE_, DFEAT, SE_);
    }

    build_x_kernel<<<(int)(((long)T_*BATCH*DMODEL + 255)/256), 256>>>(hg, times, x, xh, xl);

    const float attScale = 1.0f / sqrtf((float)HD);

    // ---------------- transformer layers ----------------
    for (int l = 0; l < 2; l++) {
        wsplit(t_Wqkv + (long)l*3*DMODEL*DMODEL, w0h, w0l, 3*DMODEL*DMODEL);
        wsplit(t_Wo   + (long)l*DMODEL*DMODEL,   w1h, w1l, DMODEL*DMODEL);
        wsplit(t_W1   + (long)l*DFF*DMODEL,      w2h, w2l, DFF*DMODEL);
        wsplit(t_W2   + (long)l*DMODEL*DFF,      w3h, w3l, DMODEL*DFF);

        tgemm(xh, xl, DMODEL, 0,0, w0h, DMODEL, 0,0,
              qkv, 0, 0, 3*DMODEL, 0,0, t_bqkv + (long)l*3*DMODEL, 0, 1.f, 0, 1, 1,
              MT, 3*DMODEL, DMODEL);
        repack_qk_kernel<<<(int)(((long)BATCH*NH*T_*DPAD + 255)/256), 256>>>(
            qkv, qrh, qrl, krh, krl);
        // fused: scores + masked softmax + split probs
        att_fused_kernel<<<dim3(1, 2, BATCH*NH), 256, ATT_S>>>(
            qrh, qrl, krh, lengths, atth, attl, attScale);
        convT_tran_kernel<<<dim3(T_/32, (HD+31)/32, BATCH*NH), dim3(32,8)>>>(qkv, vTth, vTtl);
        // o = att @ vTt^T  (split outputs only)
        tgemm(atth, attl, T_, (long)NH*T_*T_, (long)T_*T_,
              vTth, T_, (long)NH*HD*T_, (long)HD*T_,
              0, oh, ol, BATCH*DMODEL, DMODEL, HD,
              0, 0, 1.f, 0, NH, BATCH*NH, T_, HD, T_);
        // o2 = o @ Wo^T + bo (into qkv scratch)
        tgemm(oh, ol, DMODEL, 0,0, w1h, DMODEL, 0,0,
              qkv, 0, 0, DMODEL, 0,0, t_bo + (long)l*DMODEL, 0, 1.f, 0, 1, 1,
              MT, DMODEL, DMODEL);
        add_ln_kernel<<<MT, 256>>>(x, qkv, t_ln1g + (long)l*DMODEL,
                                   t_ln1b + (long)l*DMODEL, x, xh, xl);
        tgemm(xh, xl, DMODEL, 0,0, w2h, DMODEL, 0,0,
              0, ffh, ffl, DFF, 0,0, t_b1 + (long)l*DFF, 0, 1.f, 1, 1, 1,
              MT, DFF, DMODEL);
        tgemm(ffh, ffl, DFF, 0,0, w3h, DFF, 0,0,
              qkv, 0, 0, DMODEL, 0,0, t_b2 + (long)l*DMODEL, 0, 1.f, 0, 1, 1,
              MT, DMODEL, DFF);
        add_ln_kernel<<<MT, 256>>>(x, qkv, t_ln2g + (long)l*DMODEL,
                                   t_ln2b + (long)l*DMODEL, x, xh, xl);
    }

    // ---------------- head ----------------
    pool_kernel<<<dim3(BATCH, 4), 132>>>(x, lengths, pooled, plh, pll);
    wsplit(stat, sth, stl, BATCH*64);
    wsplit(static_W, w0h, w0l, 512*64);
    tgemm(sth, stl, 64, 0,0, w0h, 64, 0,0,
          0, plh + DMODEL, pll + DMODEL, DFINAL, 0,0,
          static_b, 0, 1.f, 0, 1, 1, BATCH, 512, 64);
    wsplit(mlp_W1, w1h, w1l, DFINAL*DFINAL);
    tgemm(plh, pll, DFINAL, 0,0, w1h, DFINAL, 0,0,
          hid, 0, 0, DFINAL, 0,0, mlp_b1, 0, 1.f, 1, 1, 1, BATCH, DFINAL, DFINAL);
    final_out_kernel<<<32, 256>>>(hid, mlp_W2, mlp_b2, out);
    (void)in_sizes; (void)n_in; (void)out_size;
}